// round 2
// baseline (speedup 1.0000x reference)
#include <cuda_runtime.h>
#include <math.h>

#define NIMG 800   // 25 slots * 32 episodes

// ---------------- scratch (device globals; no runtime allocation) ----------------
__device__ float g_bufA[(size_t)NIMG * 64 * 84 * 84];  // conv outputs (max layer1): 1.445 GB
__device__ float g_bufB[(size_t)NIMG * 64 * 42 * 42];  // pooled outputs (max): 361 MB
__device__ float g_Z[2 * NIMG * 128];                  // LSTM input projections (fwd/bwd)
__device__ float g_outs[5 * 21 * 32 * 64];             // bilstm hidden outputs
__device__ float g_ab[25 * 64 * 2];                    // per (slot,channel) BN affine

// ---------------- layer 1 conv: 84x84, Cin=3, Cout=64 ----------------
__global__ void __launch_bounds__(256) conv1_kernel(
    const float* __restrict__ xs, const float* __restrict__ xq,
    const float* __restrict__ w, const float* __restrict__ bias,
    float* __restrict__ out)
{
    const int N = 84;
    __shared__ __align__(16) float w_sh[9][3][64];
    __shared__ float in_sh[3][10][20];
    int g = blockIdx.z;
    int x0 = blockIdx.x * 16, y0 = blockIdx.y * 8;
    int tid = threadIdx.x;
    int ocg = tid >> 4, px = tid & 15;

    // weights (ky,kx,ci,oc) -> w_sh
    for (int i = tid; i < 9 * 3 * 64; i += 256) {
        int kk = i / 192, r = i % 192, cc = r / 64, oc = r % 64;
        w_sh[kk][cc][oc] = w[(size_t)(kk * 3 + cc) * 64 + oc];
    }
    // input patch (NHWC source)
    int b = g & 31, slot = g >> 5;
    const float* src = (slot < 20)
        ? (xs + (size_t)(b * 20 + slot) * 84 * 84 * 3)
        : (xq + (size_t)(b * 5 + (slot - 20)) * 84 * 84 * 3);
    for (int i = tid; i < 3 * 10 * 18; i += 256) {
        int cc = i / 180, r = i % 180, yy = r / 18, xx = r % 18;
        int gy = y0 + yy - 1, gx = x0 + xx - 1;
        float v = 0.f;
        if (gy >= 0 && gy < N && gx >= 0 && gx < N)
            v = src[(size_t)(gy * 84 + gx) * 3 + cc];
        in_sh[cc][yy][xx] = v;
    }
    __syncthreads();

    float acc[8][4];
#pragma unroll
    for (int p = 0; p < 8; p++) { acc[p][0]=0.f; acc[p][1]=0.f; acc[p][2]=0.f; acc[p][3]=0.f; }

#pragma unroll
    for (int cc = 0; cc < 3; cc++) {
#pragma unroll
        for (int kk = 0; kk < 9; kk++) {
            int ky = kk / 3, kx = kk - ky * 3;
            float4 wv = *(const float4*)&w_sh[kk][cc][ocg * 4];
#pragma unroll
            for (int p = 0; p < 8; p++) {
                float iv = in_sh[cc][p + ky][px + kx];
                acc[p][0] += iv * wv.x; acc[p][1] += iv * wv.y;
                acc[p][2] += iv * wv.z; acc[p][3] += iv * wv.w;
            }
        }
    }
#pragma unroll
    for (int c = 0; c < 4; c++) {
        int oc = ocg * 4 + c;
        float bv = bias[oc];
#pragma unroll
        for (int p = 0; p < 8; p++) {
            int oy = y0 + p, ox = x0 + px;
            if (oy < N && ox < N)
                out[((size_t)(g * 64 + oc) * N + oy) * N + ox] = acc[p][c] + bv;
        }
    }
}

// ---------------- layers 2-4 conv: Cin=64, Cout=64, planar layout ----------------
template <int N>
__global__ void __launch_bounds__(256) conv_kernel(
    const float* __restrict__ in, const float* __restrict__ w,
    const float* __restrict__ bias, float* __restrict__ out)
{
    __shared__ __align__(16) float w_sh[9][8][64];
    __shared__ float in_sh[8][10][20];
    int g = blockIdx.z;
    int x0 = blockIdx.x * 16, y0 = blockIdx.y * 8;
    int tid = threadIdx.x;
    int ocg = tid >> 4, px = tid & 15;

    float acc[8][4];
#pragma unroll
    for (int p = 0; p < 8; p++) { acc[p][0]=0.f; acc[p][1]=0.f; acc[p][2]=0.f; acc[p][3]=0.f; }

    for (int ci0 = 0; ci0 < 64; ci0 += 8) {
        for (int i = tid; i < 9 * 8 * 64; i += 256) {
            int kk = i >> 9, r = i & 511, cc = r >> 6, oc = r & 63;
            w_sh[kk][cc][oc] = w[((size_t)kk * 64 + ci0 + cc) * 64 + oc];
        }
        for (int i = tid; i < 8 * 10 * 18; i += 256) {
            int cc = i / 180, r = i % 180, yy = r / 18, xx = r % 18;
            int gy = y0 + yy - 1, gx = x0 + xx - 1;
            float v = 0.f;
            if (gy >= 0 && gy < N && gx >= 0 && gx < N)
                v = in[((size_t)(g * 64 + ci0 + cc) * N + gy) * N + gx];
            in_sh[cc][yy][xx] = v;
        }
        __syncthreads();
#pragma unroll
        for (int cc = 0; cc < 8; cc++) {
#pragma unroll
            for (int kk = 0; kk < 9; kk++) {
                int ky = kk / 3, kx = kk - ky * 3;
                float4 wv = *(const float4*)&w_sh[kk][cc][ocg * 4];
#pragma unroll
                for (int p = 0; p < 8; p++) {
                    float iv = in_sh[cc][p + ky][px + kx];
                    acc[p][0] += iv * wv.x; acc[p][1] += iv * wv.y;
                    acc[p][2] += iv * wv.z; acc[p][3] += iv * wv.w;
                }
            }
        }
        __syncthreads();
    }
#pragma unroll
    for (int c = 0; c < 4; c++) {
        int oc = ocg * 4 + c;
        float bv = bias[oc];
#pragma unroll
        for (int p = 0; p < 8; p++) {
            int oy = y0 + p, ox = x0 + px;
            if (oy < N && ox < N)
                out[((size_t)(g * 64 + oc) * N + oy) * N + ox] = acc[p][c] + bv;
        }
    }
}

// ---------------- BN stats per (slot, channel): mean/var over 32 images x N x N ----------------
template <int N>
__global__ void __launch_bounds__(256) stats_kernel(
    const float* __restrict__ conv,
    const float* __restrict__ gamma, const float* __restrict__ beta,
    float* __restrict__ ab)
{
    int slot = blockIdx.x >> 6, c = blockIdx.x & 63;
    int tid = threadIdx.x;
    const int PIX = N * N;
    const int CNT = 32 * PIX;
    float s = 0.f, s2 = 0.f;
    for (int i = tid; i < CNT; i += 256) {
        int b = i / PIX, pix = i - b * PIX;
        float v = conv[(size_t)((slot * 32 + b) * 64 + c) * PIX + pix];
        s += v; s2 += v * v;
    }
    __shared__ float sh1[256], sh2[256];
    sh1[tid] = s; sh2[tid] = s2;
    __syncthreads();
    for (int st = 128; st > 0; st >>= 1) {
        if (tid < st) { sh1[tid] += sh1[tid + st]; sh2[tid] += sh2[tid + st]; }
        __syncthreads();
    }
    if (tid == 0) {
        float inv = 1.f / (float)CNT;
        float m = sh1[0] * inv;
        float var = sh2[0] * inv - m * m;
        float sc = gamma[c] * rsqrtf(var + 1e-3f);
        ab[blockIdx.x * 2]     = sc;
        ab[blockIdx.x * 2 + 1] = beta[c] - m * sc;
    }
}

// ---------------- fused BN + ReLU + 2x2 maxpool ----------------
template <int N>
__global__ void __launch_bounds__(256) bnpool_kernel(
    const float* __restrict__ conv, const float* __restrict__ ab,
    float* __restrict__ out)
{
    const int M = N / 2;
    long idx = (long)blockIdx.x * 256 + threadIdx.x;
    const long total = (long)NIMG * 64 * M * M;
    if (idx >= total) return;
    int x = (int)(idx % M); long t = idx / M;
    int y = (int)(t % M); t /= M;
    int c = (int)(t & 63); int g = (int)(t >> 6);
    int slot = g >> 5;
    float sc = ab[(slot * 64 + c) * 2];
    float sf = ab[(slot * 64 + c) * 2 + 1];
    const float* p = conv + ((size_t)(g * 64 + c) * N + 2 * y) * N + 2 * x;
    float a0 = sc * p[0] + sf, a1 = sc * p[1] + sf;
    float a2 = sc * p[N] + sf, a3 = sc * p[N + 1] + sf;
    float v = fmaxf(fmaxf(a0, a1), fmaxf(a2, a3));
    out[idx] = fmaxf(v, 0.f);
}

// ---------------- input projection GEMM: Z[dir][g][128] = emb[g] @ W + bias ----------------
// emb index d = (y*5+x)*64 + c maps to pooled planar [g][c][y][x]
__global__ void __launch_bounds__(256) gemmz_kernel(
    const float* __restrict__ emb,
    const float* __restrict__ fk, const float* __restrict__ fb,
    const float* __restrict__ bk, const float* __restrict__ bb,
    float* __restrict__ Z)
{
    int gb = blockIdx.x;
    int dir = blockIdx.y;
    const float* W = dir ? bk : fk;
    const float* bias = dir ? bb : fb;
    float* Zo = Z + (size_t)dir * NIMG * 128;

    __shared__ float A_sh[32][33];
    __shared__ __align__(16) float B_sh[32][128];
    int tid = threadIdx.x;
    int jj = tid & 31, gg = tid >> 5;
    float acc[4][4] = {};

    for (int d0 = 0; d0 < 1600; d0 += 32) {
        for (int i = tid; i < 1024; i += 256) {
            int r = i >> 5, dd = i & 31;
            int d = d0 + dd;
            int c = d & 63, pix = d >> 6;
            A_sh[r][dd] = emb[(size_t)((gb * 32 + r) * 64 + c) * 25 + pix];
        }
        for (int i = tid; i < 4096; i += 256) {
            int dd = i >> 7, j = i & 127;
            B_sh[dd][j] = W[(size_t)(d0 + dd) * 128 + j];
        }
        __syncthreads();
#pragma unroll
        for (int dd = 0; dd < 32; dd++) {
            float4 bv = *(const float4*)&B_sh[dd][jj * 4];
#pragma unroll
            for (int r = 0; r < 4; r++) {
                float a = A_sh[gg * 4 + r][dd];
                acc[r][0] += a * bv.x; acc[r][1] += a * bv.y;
                acc[r][2] += a * bv.z; acc[r][3] += a * bv.w;
            }
        }
        __syncthreads();
    }
#pragma unroll
    for (int r = 0; r < 4; r++) {
#pragma unroll
        for (int c = 0; c < 4; c++) {
            int gi = gb * 32 + gg * 4 + r;
            int j = jj * 4 + c;
            Zo[(size_t)gi * 128 + j] = acc[r][c] + bias[j];
        }
    }
}

// ---------------- LSTM recurrence: one block per (q, dir); batch rows = 21 positions ----------------
__global__ void __launch_bounds__(672) lstm_kernel(
    const float* __restrict__ Z,
    const float* __restrict__ fr, const float* __restrict__ br,
    float* __restrict__ outs)
{
    int q = blockIdx.x, dir = blockIdx.y;
    const float* R = dir ? br : fr;
    const float* Zp = Z + (size_t)dir * NIMG * 128;

    __shared__ float Wh[32][128];
    __shared__ float h_sh[21][32], c_sh[21][32];
    int tid = threadIdx.x;
    for (int i = tid; i < 4096; i += 672) Wh[i >> 7][i & 127] = R[i];
    int p = tid >> 5, j = tid & 31;
    h_sh[p][j] = 0.f; c_sh[p][j] = 0.f;
    __syncthreads();

    int slot = (p < 20) ? p : (20 + q);
    for (int step = 0; step < 32; step++) {
        int t = dir ? (31 - step) : step;
        const float* zr = Zp + (size_t)(slot * 32 + t) * 128;
        float z0 = zr[j], z1 = zr[32 + j], z2 = zr[64 + j], z3 = zr[96 + j];
#pragma unroll
        for (int k = 0; k < 32; k++) {
            float hk = h_sh[p][k];
            z0 += hk * Wh[k][j];
            z1 += hk * Wh[k][32 + j];
            z2 += hk * Wh[k][64 + j];
            z3 += hk * Wh[k][96 + j];
        }
        float ig = 1.f / (1.f + expf(-z0));
        float fg = 1.f / (1.f + expf(-z1));
        float gg = tanhf(z2);
        float og = 1.f / (1.f + expf(-z3));
        float cn = fg * c_sh[p][j] + ig * gg;
        float hn = og * tanhf(cn);
        __syncthreads();
        h_sh[p][j] = hn; c_sh[p][j] = cn;
        outs[(size_t)((q * 21 + p) * 32 + t) * 64 + dir * 32 + j] = hn;
        __syncthreads();
    }
}

// ---------------- attention + softmax + CE + acc ----------------
__global__ void __launch_bounds__(256) final_kernel(
    const float* __restrict__ outs,
    const int* __restrict__ ysup, const int* __restrict__ yqry,
    float* __restrict__ out)
{
    __shared__ float ce_sh[160], eq_sh[160];
    int tid = threadIdx.x;
    if (tid < 160) {
        int q = tid / 32, b = tid % 32;
        const float* qry = outs + (size_t)((q * 21 + 20) * 32 + b) * 64;
        float logit[20];
        for (int s = 0; s < 20; s++) {
            const float* sp = outs + (size_t)((q * 21 + s) * 32 + b) * 64;
            float d = 0.f, n2 = 0.f;
            for (int k = 0; k < 64; k++) { d += qry[k] * sp[k]; n2 += sp[k] * sp[k]; }
            logit[s] = d * rsqrtf(fmaxf(n2, 1e-10f));
        }
        float mx = logit[0];
        for (int s = 1; s < 20; s++) mx = fmaxf(mx, logit[s]);
        float den = 0.f;
        for (int s = 0; s < 20; s++) { logit[s] = expf(logit[s] - mx); den += logit[s]; }
        float invden = 1.f / den;
        float preds[20];
        for (int w = 0; w < 20; w++) preds[w] = 0.f;
        for (int s = 0; s < 20; s++) preds[ysup[b * 20 + s]] += logit[s] * invden;
        int yq = yqry[b * 5 + q];
        float pv = fminf(fmaxf(preds[yq], 1e-7f), 1.f - 1e-7f);
        ce_sh[tid] = -logf(pv);
        int best = 0;
        for (int w = 1; w < 20; w++) if (preds[w] > preds[best]) best = w;
        eq_sh[tid] = (best == yq) ? 1.f : 0.f;
    }
    __syncthreads();
    if (tid < 32) {
        float s = 0.f;
        for (int q = 0; q < 5; q++) s += ce_sh[q * 32 + tid];
        out[tid] = s * 0.2f;
    }
    if (tid == 0) {
        float s = 0.f;
        for (int i = 0; i < 160; i++) s += eq_sh[i];
        out[32] = s / 160.f;
    }
}

// ---------------- launch ----------------
extern "C" void kernel_launch(void* const* d_in, const int* in_sizes, int n_in,
                              void* d_out, int out_size)
{
    (void)in_sizes; (void)n_in; (void)out_size;
    const float* xs   = (const float*)d_in[0];
    const int*   ysup = (const int*)  d_in[1];
    const float* xq   = (const float*)d_in[2];
    const int*   yqry = (const int*)  d_in[3];
    const float* k1 = (const float*)d_in[4];
    const float* b1 = (const float*)d_in[5];
    const float* g1 = (const float*)d_in[6];
    const float* be1 = (const float*)d_in[7];
    const float* k2 = (const float*)d_in[8];
    const float* b2 = (const float*)d_in[9];
    const float* g2 = (const float*)d_in[10];
    const float* be2 = (const float*)d_in[11];
    const float* k3 = (const float*)d_in[12];
    const float* b3 = (const float*)d_in[13];
    const float* g3 = (const float*)d_in[14];
    const float* be3 = (const float*)d_in[15];
    const float* k4 = (const float*)d_in[16];
    const float* b4 = (const float*)d_in[17];
    const float* g4 = (const float*)d_in[18];
    const float* be4 = (const float*)d_in[19];
    const float* fk = (const float*)d_in[20];
    const float* fr = (const float*)d_in[21];
    const float* fb = (const float*)d_in[22];
    const float* bk = (const float*)d_in[23];
    const float* br = (const float*)d_in[24];
    const float* bb = (const float*)d_in[25];

    float *bufA, *bufB, *Z, *outs, *ab;
    cudaGetSymbolAddress((void**)&bufA, g_bufA);
    cudaGetSymbolAddress((void**)&bufB, g_bufB);
    cudaGetSymbolAddress((void**)&Z,    g_Z);
    cudaGetSymbolAddress((void**)&outs, g_outs);
    cudaGetSymbolAddress((void**)&ab,   g_ab);

    // layer 1: 84 -> pool 42
    conv1_kernel<<<dim3(6, 11, NIMG), 256>>>(xs, xq, k1, b1, bufA);
    stats_kernel<84><<<25 * 64, 256>>>(bufA, g1, be1, ab);
    bnpool_kernel<84><<<(NIMG * 64 * 42 * 42 + 255) / 256, 256>>>(bufA, ab, bufB);
    // layer 2: 42 -> pool 21
    conv_kernel<42><<<dim3(3, 6, NIMG), 256>>>(bufB, k2, b2, bufA);
    stats_kernel<42><<<25 * 64, 256>>>(bufA, g2, be2, ab);
    bnpool_kernel<42><<<(NIMG * 64 * 21 * 21 + 255) / 256, 256>>>(bufA, ab, bufB);
    // layer 3: 21 -> pool 10
    conv_kernel<21><<<dim3(2, 3, NIMG), 256>>>(bufB, k3, b3, bufA);
    stats_kernel<21><<<25 * 64, 256>>>(bufA, g3, be3, ab);
    bnpool_kernel<21><<<(NIMG * 64 * 10 * 10 + 255) / 256, 256>>>(bufA, ab, bufB);
    // layer 4: 10 -> pool 5
    conv_kernel<10><<<dim3(1, 2, NIMG), 256>>>(bufB, k4, b4, bufA);
    stats_kernel<10><<<25 * 64, 256>>>(bufA, g4, be4, ab);
    bnpool_kernel<10><<<(NIMG * 64 * 5 * 5 + 255) / 256, 256>>>(bufA, ab, bufB);

    // LSTM input projections (both directions), bias folded in
    gemmz_kernel<<<dim3(25, 2), 256>>>(bufB, fk, fb, bk, bb, Z);
    // recurrence: one block per (q, dir)
    lstm_kernel<<<dim3(5, 2), 672>>>(Z, fr, br, outs);
    // attention + CE + acc
    final_kernel<<<1, 256>>>(outs, ysup, yqry, (float*)d_out);
}

// round 3
// speedup vs baseline: 1.2707x; 1.2707x over previous
#include <cuda_runtime.h>
#include <math.h>

#define NIMG 800   // 25 slots * 32 episodes
typedef unsigned long long u64;

// ---------------- scratch (device globals; no runtime allocation) ----------------
__device__ float g_bufA[(size_t)NIMG * 64 * 42 * 42];  // pooled raw (layers 1,3)
__device__ float g_bufB[(size_t)NIMG * 64 * 21 * 21];  // pooled raw (layers 2,4)
__device__ float g_part[(size_t)NIMG * 66 * 64 * 2];   // per-block BN partial sums
__device__ float g_Z[2 * NIMG * 128];                  // LSTM input projections (fwd/bwd)
__device__ float g_outs[5 * 21 * 32 * 64];             // bilstm hidden outputs
__device__ float g_ab[25 * 64 * 2];                    // per (slot,channel) BN affine

// ---------------- f32x2 packed helpers ----------------
__device__ __forceinline__ u64 pack_dup(float v) {
    u64 r; asm("mov.b64 %0, {%1, %1};" : "=l"(r) : "f"(v)); return r;
}
__device__ __forceinline__ void ffma2(u64& acc, u64 a, u64 b) {
    asm("fma.rn.f32x2 %0, %1, %2, %0;" : "+l"(acc) : "l"(a), "l"(b));
}
__device__ __forceinline__ void unpack2(u64 v, float& lo, float& hi) {
    asm("mov.b64 {%0, %1}, %2;" : "=f"(lo), "=f"(hi) : "l"(v));
}

// ---------------- shared epilogue: stats partials + pre-BN 2x2 maxpool ----------------
// acc[p][j]: p = y-row within 8-row tile, j = oc pair (oc0+2j, oc0+2j+1), bias included.
template <int N>
__device__ __forceinline__ void conv_epilogue(
    u64 (&acc)[8][4], int g, int x0, int y0, int px, int oc0,
    float* __restrict__ pooled, float* __restrict__ part)
{
    const int Np = N / 2;
    int T = gridDim.x * gridDim.y;
    int tile = blockIdx.y * gridDim.x + blockIdx.x;
    bool xv = (x0 + px) < N;
    float* partp = part + ((size_t)(g * T + tile) * 64 + oc0) * 2;
    int pooly0 = y0 >> 1;
    int poolx = (x0 + px) >> 1;

#pragma unroll
    for (int j = 0; j < 4; j++) {
        float s0 = 0.f, s1 = 0.f, q0 = 0.f, q1 = 0.f;
        float m0[4], m1[4];
#pragma unroll
        for (int jj = 0; jj < 4; jj++) { m0[jj] = -1e30f; m1[jj] = -1e30f; }
#pragma unroll
        for (int p = 0; p < 8; p++) {
            float v0, v1; unpack2(acc[p][j], v0, v1);
            if (xv && (y0 + p) < N) {
                s0 += v0; q0 += v0 * v0;
                s1 += v1; q1 += v1 * v1;
            }
            m0[p >> 1] = fmaxf(m0[p >> 1], v0);
            m1[p >> 1] = fmaxf(m1[p >> 1], v1);
        }
#pragma unroll
        for (int off = 8; off; off >>= 1) {
            s0 += __shfl_down_sync(0xffffffffu, s0, off, 16);
            s1 += __shfl_down_sync(0xffffffffu, s1, off, 16);
            q0 += __shfl_down_sync(0xffffffffu, q0, off, 16);
            q1 += __shfl_down_sync(0xffffffffu, q1, off, 16);
        }
        if (px == 0) {
            partp[(2 * j) * 2]         = s0;
            partp[(2 * j) * 2 + 1]     = q0;
            partp[(2 * j + 1) * 2]     = s1;
            partp[(2 * j + 1) * 2 + 1] = q1;
        }
#pragma unroll
        for (int jj = 0; jj < 4; jj++) {
            float o0 = __shfl_xor_sync(0xffffffffu, m0[jj], 1);
            float o1 = __shfl_xor_sync(0xffffffffu, m1[jj], 1);
            if (!(px & 1)) {
                int py = pooly0 + jj;
                if (py < Np && poolx < Np) {
                    float r0 = fmaxf(m0[jj], o0), r1 = fmaxf(m1[jj], o1);
                    pooled[((size_t)(g * 64 + oc0 + 2 * j) * Np + py) * Np + poolx] = r0;
                    pooled[((size_t)(g * 64 + oc0 + 2 * j + 1) * Np + py) * Np + poolx] = r1;
                }
            }
        }
    }
}

// ---------------- layer 1: conv 84x84 Cin=3 + stats partials + pre-BN pool ----------------
__global__ void __launch_bounds__(128, 4) convpool1_kernel(
    const float* __restrict__ xs, const float* __restrict__ xq,
    const float* __restrict__ w, const float* __restrict__ bias,
    float* __restrict__ pooled, float* __restrict__ part)
{
    const int N = 84;
    __shared__ __align__(16) float w_sh[9][3][64];
    __shared__ float in_sh[3][10][20];
    int g = blockIdx.z;
    int x0 = blockIdx.x * 16, y0 = blockIdx.y * 8;
    int tid = threadIdx.x;
    int px = tid & 15, ocg = tid >> 4;
    int oc0 = ocg * 8;

    u64 acc[8][4];
    {
        ulonglong2 bp0 = *(const ulonglong2*)&bias[oc0];
        ulonglong2 bp1 = *(const ulonglong2*)&bias[oc0 + 4];
#pragma unroll
        for (int p = 0; p < 8; p++) {
            acc[p][0] = bp0.x; acc[p][1] = bp0.y;
            acc[p][2] = bp1.x; acc[p][3] = bp1.y;
        }
    }

    for (int i = tid; i < 9 * 3 * 64; i += 128) {
        int kk = i / 192, r = i % 192, cc = r / 64, oc = r % 64;
        w_sh[kk][cc][oc] = w[(size_t)(kk * 3 + cc) * 64 + oc];
    }
    int b = g & 31, slot = g >> 5;
    const float* src = (slot < 20)
        ? (xs + (size_t)(b * 20 + slot) * 84 * 84 * 3)
        : (xq + (size_t)(b * 5 + (slot - 20)) * 84 * 84 * 3);
    for (int i = tid; i < 3 * 10 * 18; i += 128) {
        int cc = i / 180, r = i % 180, yy = r / 18, xx = r % 18;
        int gy = y0 + yy - 1, gx = x0 + xx - 1;
        float v = 0.f;
        if (gy >= 0 && gy < N && gx >= 0 && gx < N)
            v = src[(size_t)(gy * 84 + gx) * 3 + cc];
        in_sh[cc][yy][xx] = v;
    }
    __syncthreads();

#pragma unroll
    for (int cc = 0; cc < 3; cc++) {
#pragma unroll
        for (int kx = 0; kx < 3; kx++) {
            u64 a[10];
#pragma unroll
            for (int r = 0; r < 10; r++) a[r] = pack_dup(in_sh[cc][r][px + kx]);
#pragma unroll
            for (int ky = 0; ky < 3; ky++) {
                int kk = ky * 3 + kx;
                ulonglong2 w01 = *(const ulonglong2*)&w_sh[kk][cc][oc0];
                ulonglong2 w23 = *(const ulonglong2*)&w_sh[kk][cc][oc0 + 4];
#pragma unroll
                for (int p = 0; p < 8; p++) {
                    ffma2(acc[p][0], a[p + ky], w01.x);
                    ffma2(acc[p][1], a[p + ky], w01.y);
                    ffma2(acc[p][2], a[p + ky], w23.x);
                    ffma2(acc[p][3], a[p + ky], w23.y);
                }
            }
        }
    }
    conv_epilogue<84>(acc, g, x0, y0, px, oc0, pooled, part);
}

// ---------------- layers 2-4: conv Cin=64 on pooled-raw input (BN+ReLU applied on load) ----------------
template <int N>
__global__ void __launch_bounds__(128, 4) convpool_kernel(
    const float* __restrict__ in, const float* __restrict__ abp,
    const float* __restrict__ w, const float* __restrict__ bias,
    float* __restrict__ pooled, float* __restrict__ part)
{
    __shared__ __align__(16) float w_sh[9][8][64];
    __shared__ float in_sh[8][10][20];
    int g = blockIdx.z, slot = g >> 5;
    int x0 = blockIdx.x * 16, y0 = blockIdx.y * 8;
    int tid = threadIdx.x;
    int px = tid & 15, ocg = tid >> 4;
    int oc0 = ocg * 8;

    u64 acc[8][4];
    {
        ulonglong2 bp0 = *(const ulonglong2*)&bias[oc0];
        ulonglong2 bp1 = *(const ulonglong2*)&bias[oc0 + 4];
#pragma unroll
        for (int p = 0; p < 8; p++) {
            acc[p][0] = bp0.x; acc[p][1] = bp0.y;
            acc[p][2] = bp1.x; acc[p][3] = bp1.y;
        }
    }

    for (int ci0 = 0; ci0 < 64; ci0 += 8) {
        for (int i = tid; i < 9 * 8 * 64; i += 128) {
            int kk = i >> 9, r = i & 511, cc = r >> 6, oc = r & 63;
            w_sh[kk][cc][oc] = w[((size_t)kk * 64 + ci0 + cc) * 64 + oc];
        }
        for (int i = tid; i < 8 * 10 * 18; i += 128) {
            int cc = i / 180, r = i % 180, yy = r / 18, xx = r % 18;
            int gy = y0 + yy - 1, gx = x0 + xx - 1;
            float v = 0.f;
            if (gy >= 0 && gy < N && gx >= 0 && gx < N) {
                float raw = in[((size_t)(g * 64 + ci0 + cc) * N + gy) * N + gx];
                float sc = abp[(slot * 64 + ci0 + cc) * 2];
                float sf = abp[(slot * 64 + ci0 + cc) * 2 + 1];
                v = fmaxf(sc * raw + sf, 0.f);
            }
            in_sh[cc][yy][xx] = v;
        }
        __syncthreads();
#pragma unroll
        for (int cc = 0; cc < 8; cc++) {
#pragma unroll
            for (int kx = 0; kx < 3; kx++) {
                u64 a[10];
#pragma unroll
                for (int r = 0; r < 10; r++) a[r] = pack_dup(in_sh[cc][r][px + kx]);
#pragma unroll
                for (int ky = 0; ky < 3; ky++) {
                    int kk = ky * 3 + kx;
                    ulonglong2 w01 = *(const ulonglong2*)&w_sh[kk][cc][oc0];
                    ulonglong2 w23 = *(const ulonglong2*)&w_sh[kk][cc][oc0 + 4];
#pragma unroll
                    for (int p = 0; p < 8; p++) {
                        ffma2(acc[p][0], a[p + ky], w01.x);
                        ffma2(acc[p][1], a[p + ky], w01.y);
                        ffma2(acc[p][2], a[p + ky], w23.x);
                        ffma2(acc[p][3], a[p + ky], w23.y);
                    }
                }
            }
        }
        __syncthreads();
    }
    conv_epilogue<N>(acc, g, x0, y0, px, oc0, pooled, part);
}

// ---------------- reduce partials -> BN affine (scale, shift) ----------------
__global__ void __launch_bounds__(256) abreduce_kernel(
    const float* __restrict__ part,
    const float* __restrict__ gamma, const float* __restrict__ beta,
    float* __restrict__ ab, int T, float invCnt)
{
    int slot = blockIdx.x >> 6, c = blockIdx.x & 63;
    int tid = threadIdx.x;
    float s = 0.f, q = 0.f;
    int total = 32 * T;
    for (int i = tid; i < total; i += 256) {
        int b = i / T, t = i % T;
        const float* p = part + ((size_t)((slot * 32 + b) * T + t) * 64 + c) * 2;
        s += p[0]; q += p[1];
    }
    __shared__ float sh1[256], sh2[256];
    sh1[tid] = s; sh2[tid] = q;
    __syncthreads();
    for (int st = 128; st > 0; st >>= 1) {
        if (tid < st) { sh1[tid] += sh1[tid + st]; sh2[tid] += sh2[tid + st]; }
        __syncthreads();
    }
    if (tid == 0) {
        float m = sh1[0] * invCnt;
        float var = sh2[0] * invCnt - m * m;
        float sc = gamma[c] * rsqrtf(var + 1e-3f);
        ab[blockIdx.x * 2]     = sc;
        ab[blockIdx.x * 2 + 1] = beta[c] - m * sc;
    }
}

// ---------------- input projection GEMM: Z[dir][g][128] = relu(a4*raw+b4) @ W + bias ----------------
__global__ void __launch_bounds__(256) gemmz_kernel(
    const float* __restrict__ emb, const float* __restrict__ abp,
    const float* __restrict__ fk, const float* __restrict__ fb,
    const float* __restrict__ bk, const float* __restrict__ bb,
    float* __restrict__ Z)
{
    int gb = blockIdx.x;
    int dir = blockIdx.y;
    const float* W = dir ? bk : fk;
    const float* bias = dir ? bb : fb;
    float* Zo = Z + (size_t)dir * NIMG * 128;

    __shared__ float A_sh[32][33];
    __shared__ __align__(16) float B_sh[32][128];
    int tid = threadIdx.x;
    int jj = tid & 31, gg = tid >> 5;
    float acc[4][4] = {};

    for (int d0 = 0; d0 < 1600; d0 += 32) {
        for (int i = tid; i < 1024; i += 256) {
            int r = i >> 5, dd = i & 31;
            int d = d0 + dd;
            int c = d & 63, pix = d >> 6;
            float raw = emb[(size_t)((gb * 32 + r) * 64 + c) * 25 + pix];
            float sc = abp[(gb * 64 + c) * 2];
            float sf = abp[(gb * 64 + c) * 2 + 1];
            A_sh[r][dd] = fmaxf(sc * raw + sf, 0.f);
        }
        for (int i = tid; i < 4096; i += 256) {
            int dd = i >> 7, j = i & 127;
            B_sh[dd][j] = W[(size_t)(d0 + dd) * 128 + j];
        }
        __syncthreads();
#pragma unroll
        for (int dd = 0; dd < 32; dd++) {
            float4 bv = *(const float4*)&B_sh[dd][jj * 4];
#pragma unroll
            for (int r = 0; r < 4; r++) {
                float a = A_sh[gg * 4 + r][dd];
                acc[r][0] += a * bv.x; acc[r][1] += a * bv.y;
                acc[r][2] += a * bv.z; acc[r][3] += a * bv.w;
            }
        }
        __syncthreads();
    }
#pragma unroll
    for (int r = 0; r < 4; r++) {
#pragma unroll
        for (int c = 0; c < 4; c++) {
            int gi = gb * 32 + gg * 4 + r;
            int j = jj * 4 + c;
            Zo[(size_t)gi * 128 + j] = acc[r][c] + bias[j];
        }
    }
}

// ---------------- LSTM recurrence: one block per (q, dir); batch rows = 21 positions ----------------
__global__ void __launch_bounds__(672) lstm_kernel(
    const float* __restrict__ Z,
    const float* __restrict__ fr, const float* __restrict__ br,
    float* __restrict__ outs)
{
    int q = blockIdx.x, dir = blockIdx.y;
    const float* R = dir ? br : fr;
    const float* Zp = Z + (size_t)dir * NIMG * 128;

    __shared__ float Wh[32][128];
    __shared__ float h_sh[21][32], c_sh[21][32];
    int tid = threadIdx.x;
    for (int i = tid; i < 4096; i += 672) Wh[i >> 7][i & 127] = R[i];
    int p = tid >> 5, j = tid & 31;
    h_sh[p][j] = 0.f; c_sh[p][j] = 0.f;
    __syncthreads();

    int slot = (p < 20) ? p : (20 + q);
    for (int step = 0; step < 32; step++) {
        int t = dir ? (31 - step) : step;
        const float* zr = Zp + (size_t)(slot * 32 + t) * 128;
        float z0 = zr[j], z1 = zr[32 + j], z2 = zr[64 + j], z3 = zr[96 + j];
#pragma unroll
        for (int k = 0; k < 32; k++) {
            float hk = h_sh[p][k];
            z0 += hk * Wh[k][j];
            z1 += hk * Wh[k][32 + j];
            z2 += hk * Wh[k][64 + j];
            z3 += hk * Wh[k][96 + j];
        }
        float ig = 1.f / (1.f + expf(-z0));
        float fg = 1.f / (1.f + expf(-z1));
        float gg = tanhf(z2);
        float og = 1.f / (1.f + expf(-z3));
        float cn = fg * c_sh[p][j] + ig * gg;
        float hn = og * tanhf(cn);
        __syncthreads();
        h_sh[p][j] = hn; c_sh[p][j] = cn;
        outs[(size_t)((q * 21 + p) * 32 + t) * 64 + dir * 32 + j] = hn;
        __syncthreads();
    }
}

// ---------------- attention + softmax + CE + acc ----------------
__global__ void __launch_bounds__(256) final_kernel(
    const float* __restrict__ outs,
    const int* __restrict__ ysup, const int* __restrict__ yqry,
    float* __restrict__ out)
{
    __shared__ float ce_sh[160], eq_sh[160];
    int tid = threadIdx.x;
    if (tid < 160) {
        int q = tid / 32, b = tid % 32;
        const float* qry = outs + (size_t)((q * 21 + 20) * 32 + b) * 64;
        float logit[20];
        for (int s = 0; s < 20; s++) {
            const float* sp = outs + (size_t)((q * 21 + s) * 32 + b) * 64;
            float d = 0.f, n2 = 0.f;
            for (int k = 0; k < 64; k++) { d += qry[k] * sp[k]; n2 += sp[k] * sp[k]; }
            logit[s] = d * rsqrtf(fmaxf(n2, 1e-10f));
        }
        float mx = logit[0];
        for (int s = 1; s < 20; s++) mx = fmaxf(mx, logit[s]);
        float den = 0.f;
        for (int s = 0; s < 20; s++) { logit[s] = expf(logit[s] - mx); den += logit[s]; }
        float invden = 1.f / den;
        float preds[20];
        for (int w = 0; w < 20; w++) preds[w] = 0.f;
        for (int s = 0; s < 20; s++) preds[ysup[b * 20 + s]] += logit[s] * invden;
        int yq = yqry[b * 5 + q];
        float pv = fminf(fmaxf(preds[yq], 1e-7f), 1.f - 1e-7f);
        ce_sh[tid] = -logf(pv);
        int best = 0;
        for (int w = 1; w < 20; w++) if (preds[w] > preds[best]) best = w;
        eq_sh[tid] = (best == yq) ? 1.f : 0.f;
    }
    __syncthreads();
    if (tid < 32) {
        float s = 0.f;
        for (int q = 0; q < 5; q++) s += ce_sh[q * 32 + tid];
        out[tid] = s * 0.2f;
    }
    if (tid == 0) {
        float s = 0.f;
        for (int i = 0; i < 160; i++) s += eq_sh[i];
        out[32] = s / 160.f;
    }
}

// ---------------- launch ----------------
extern "C" void kernel_launch(void* const* d_in, const int* in_sizes, int n_in,
                              void* d_out, int out_size)
{
    (void)in_sizes; (void)n_in; (void)out_size;
    const float* xs   = (const float*)d_in[0];
    const int*   ysup = (const int*)  d_in[1];
    const float* xq   = (const float*)d_in[2];
    const int*   yqry = (const int*)  d_in[3];
    const float* k1 = (const float*)d_in[4];
    const float* b1 = (const float*)d_in[5];
    const float* g1 = (const float*)d_in[6];
    const float* be1 = (const float*)d_in[7];
    const float* k2 = (const float*)d_in[8];
    const float* b2 = (const float*)d_in[9];
    const float* g2 = (const float*)d_in[10];
    const float* be2 = (const float*)d_in[11];
    const float* k3 = (const float*)d_in[12];
    const float* b3 = (const float*)d_in[13];
    const float* g3 = (const float*)d_in[14];
    const float* be3 = (const float*)d_in[15];
    const float* k4 = (const float*)d_in[16];
    const float* b4 = (const float*)d_in[17];
    const float* g4 = (const float*)d_in[18];
    const float* be4 = (const float*)d_in[19];
    const float* fk = (const float*)d_in[20];
    const float* fr = (const float*)d_in[21];
    const float* fb = (const float*)d_in[22];
    const float* bk = (const float*)d_in[23];
    const float* br = (const float*)d_in[24];
    const float* bb = (const float*)d_in[25];

    float *bufA, *bufB, *part, *Z, *outs, *ab;
    cudaGetSymbolAddress((void**)&bufA, g_bufA);
    cudaGetSymbolAddress((void**)&bufB, g_bufB);
    cudaGetSymbolAddress((void**)&part, g_part);
    cudaGetSymbolAddress((void**)&Z,    g_Z);
    cudaGetSymbolAddress((void**)&outs, g_outs);
    cudaGetSymbolAddress((void**)&ab,   g_ab);

    // layer 1: 84 -> pooled raw 42 (bufA), T=66
    convpool1_kernel<<<dim3(6, 11, NIMG), 128>>>(xs, xq, k1, b1, bufA, part);
    abreduce_kernel<<<25 * 64, 256>>>(part, g1, be1, ab, 66, 1.f / (32.f * 84.f * 84.f));
    // layer 2: 42 -> pooled raw 21 (bufB), T=18
    convpool_kernel<42><<<dim3(3, 6, NIMG), 128>>>(bufA, ab, k2, b2, bufB, part);
    abreduce_kernel<<<25 * 64, 256>>>(part, g2, be2, ab, 18, 1.f / (32.f * 42.f * 42.f));
    // layer 3: 21 -> pooled raw 10 (bufA), T=6
    convpool_kernel<21><<<dim3(2, 3, NIMG), 128>>>(bufB, ab, k3, b3, bufA, part);
    abreduce_kernel<<<25 * 64, 256>>>(part, g3, be3, ab, 6, 1.f / (32.f * 21.f * 21.f));
    // layer 4: 10 -> pooled raw 5 (bufB), T=2
    convpool_kernel<10><<<dim3(1, 2, NIMG), 128>>>(bufA, ab, k4, b4, bufB, part);
    abreduce_kernel<<<25 * 64, 256>>>(part, g4, be4, ab, 2, 1.f / (32.f * 10.f * 10.f));

    // LSTM input projections (both directions); BN+ReLU of layer 4 applied on load
    gemmz_kernel<<<dim3(25, 2), 256>>>(bufB, ab, fk, fb, bk, bb, Z);
    // recurrence: one block per (q, dir)
    lstm_kernel<<<dim3(5, 2), 672>>>(Z, fr, br, outs);
    // attention + CE + acc
    final_kernel<<<1, 256>>>(outs, ysup, yqry, (float*)d_out);
}

// round 4
// speedup vs baseline: 1.2710x; 1.0002x over previous
#include <cuda_runtime.h>
#include <math.h>

#define NIMG 800   // 25 slots * 32 episodes
typedef unsigned long long u64;

// ---------------- scratch (device globals; no runtime allocation) ----------------
__device__ float g_bufA[(size_t)NIMG * 64 * 42 * 42];  // pooled raw (layers 1,3)
__device__ float g_bufB[(size_t)NIMG * 64 * 21 * 21];  // pooled raw (layers 2,4)
__device__ float g_part[(size_t)NIMG * 66 * 64 * 2];   // per-block BN partial sums
__device__ float g_Z[2 * NIMG * 128];                  // LSTM input projections (fwd/bwd)
__device__ float g_outs[5 * 21 * 32 * 64];             // bilstm hidden outputs
__device__ float g_ab[25 * 64 * 2];                    // per (slot,channel) BN affine

// ---------------- f32x2 packed helpers ----------------
__device__ __forceinline__ u64 pack_dup(float v) {
    u64 r; asm("mov.b64 %0, {%1, %1};" : "=l"(r) : "f"(v)); return r;
}
__device__ __forceinline__ void ffma2(u64& acc, u64 a, u64 b) {
    asm("fma.rn.f32x2 %0, %1, %2, %0;" : "+l"(acc) : "l"(a), "l"(b));
}
__device__ __forceinline__ void unpack2(u64 v, float& lo, float& hi) {
    asm("mov.b64 {%0, %1}, %2;" : "=f"(lo), "=f"(hi) : "l"(v));
}

// ---------------- shared epilogue: stats partials + pre-BN 2x2 maxpool ----------------
// acc[p][j]: p = y-row within 8-row tile, j = oc pair (oc0+2j, oc0+2j+1), bias included.
template <int N>
__device__ __forceinline__ void conv_epilogue(
    u64 (&acc)[8][4], int g, int x0, int y0, int px, int oc0,
    float* __restrict__ pooled, float* __restrict__ part)
{
    const int Np = N / 2;
    int T = gridDim.x * gridDim.y;
    int tile = blockIdx.y * gridDim.x + blockIdx.x;
    bool xv = (x0 + px) < N;
    float* partp = part + ((size_t)(g * T + tile) * 64 + oc0) * 2;
    int pooly0 = y0 >> 1;
    int poolx = (x0 + px) >> 1;

#pragma unroll
    for (int j = 0; j < 4; j++) {
        float s0 = 0.f, s1 = 0.f, q0 = 0.f, q1 = 0.f;
        float m0[4], m1[4];
#pragma unroll
        for (int jj = 0; jj < 4; jj++) { m0[jj] = -1e30f; m1[jj] = -1e30f; }
#pragma unroll
        for (int p = 0; p < 8; p++) {
            float v0, v1; unpack2(acc[p][j], v0, v1);
            if (xv && (y0 + p) < N) {
                s0 += v0; q0 += v0 * v0;
                s1 += v1; q1 += v1 * v1;
            }
            m0[p >> 1] = fmaxf(m0[p >> 1], v0);
            m1[p >> 1] = fmaxf(m1[p >> 1], v1);
        }
#pragma unroll
        for (int off = 8; off; off >>= 1) {
            s0 += __shfl_down_sync(0xffffffffu, s0, off, 16);
            s1 += __shfl_down_sync(0xffffffffu, s1, off, 16);
            q0 += __shfl_down_sync(0xffffffffu, q0, off, 16);
            q1 += __shfl_down_sync(0xffffffffu, q1, off, 16);
        }
        if (px == 0) {
            partp[(2 * j) * 2]         = s0;
            partp[(2 * j) * 2 + 1]     = q0;
            partp[(2 * j + 1) * 2]     = s1;
            partp[(2 * j + 1) * 2 + 1] = q1;
        }
#pragma unroll
        for (int jj = 0; jj < 4; jj++) {
            float o0 = __shfl_xor_sync(0xffffffffu, m0[jj], 1);
            float o1 = __shfl_xor_sync(0xffffffffu, m1[jj], 1);
            if (!(px & 1)) {
                int py = pooly0 + jj;
                if (py < Np && poolx < Np) {
                    float r0 = fmaxf(m0[jj], o0), r1 = fmaxf(m1[jj], o1);
                    pooled[((size_t)(g * 64 + oc0 + 2 * j) * Np + py) * Np + poolx] = r0;
                    pooled[((size_t)(g * 64 + oc0 + 2 * j + 1) * Np + py) * Np + poolx] = r1;
                }
            }
        }
    }
}

// ---------------- layer 1: conv 84x84 Cin=3 + stats partials + pre-BN pool ----------------
__global__ void __launch_bounds__(128, 4) convpool1_kernel(
    const float* __restrict__ xs, const float* __restrict__ xq,
    const float* __restrict__ w, const float* __restrict__ bias,
    float* __restrict__ pooled, float* __restrict__ part)
{
    const int N = 84;
    __shared__ __align__(16) float w_sh[9][3][64];
    __shared__ float in_sh[3][10][20];
    int g = blockIdx.z;
    int x0 = blockIdx.x * 16, y0 = blockIdx.y * 8;
    int tid = threadIdx.x;
    int px = tid & 15, ocg = tid >> 4;
    int oc0 = ocg * 8;

    u64 acc[8][4];
    {
        ulonglong2 bp0 = *(const ulonglong2*)&bias[oc0];
        ulonglong2 bp1 = *(const ulonglong2*)&bias[oc0 + 4];
#pragma unroll
        for (int p = 0; p < 8; p++) {
            acc[p][0] = bp0.x; acc[p][1] = bp0.y;
            acc[p][2] = bp1.x; acc[p][3] = bp1.y;
        }
    }

    for (int i = tid; i < 9 * 3 * 64; i += 128) {
        int kk = i / 192, r = i % 192, cc = r / 64, oc = r % 64;
        w_sh[kk][cc][oc] = w[(size_t)(kk * 3 + cc) * 64 + oc];
    }
    int b = g & 31, slot = g >> 5;
    const float* src = (slot < 20)
        ? (xs + (size_t)(b * 20 + slot) * 84 * 84 * 3)
        : (xq + (size_t)(b * 5 + (slot - 20)) * 84 * 84 * 3);
    for (int i = tid; i < 3 * 10 * 18; i += 128) {
        int cc = i / 180, r = i % 180, yy = r / 18, xx = r % 18;
        int gy = y0 + yy - 1, gx = x0 + xx - 1;
        float v = 0.f;
        if (gy >= 0 && gy < N && gx >= 0 && gx < N)
            v = src[(size_t)(gy * 84 + gx) * 3 + cc];
        in_sh[cc][yy][xx] = v;
    }
    __syncthreads();

#pragma unroll
    for (int cc = 0; cc < 3; cc++) {
#pragma unroll
        for (int kx = 0; kx < 3; kx++) {
            u64 a[10];
#pragma unroll
            for (int r = 0; r < 10; r++) a[r] = pack_dup(in_sh[cc][r][px + kx]);
#pragma unroll
            for (int ky = 0; ky < 3; ky++) {
                int kk = ky * 3 + kx;
                ulonglong2 w01 = *(const ulonglong2*)&w_sh[kk][cc][oc0];
                ulonglong2 w23 = *(const ulonglong2*)&w_sh[kk][cc][oc0 + 4];
#pragma unroll
                for (int p = 0; p < 8; p++) {
                    ffma2(acc[p][0], a[p + ky], w01.x);
                    ffma2(acc[p][1], a[p + ky], w01.y);
                    ffma2(acc[p][2], a[p + ky], w23.x);
                    ffma2(acc[p][3], a[p + ky], w23.y);
                }
            }
        }
    }
    conv_epilogue<84>(acc, g, x0, y0, px, oc0, pooled, part);
}

// ---------------- layers 2-4: conv Cin=64 on pooled-raw input (BN+ReLU applied on load) ----------------
template <int N>
__global__ void __launch_bounds__(128, 4) convpool_kernel(
    const float* __restrict__ in, const float* __restrict__ abp,
    const float* __restrict__ w, const float* __restrict__ bias,
    float* __restrict__ pooled, float* __restrict__ part)
{
    __shared__ __align__(16) float w_sh[9][8][64];
    __shared__ float in_sh[8][10][20];
    int g = blockIdx.z, slot = g >> 5;
    int x0 = blockIdx.x * 16, y0 = blockIdx.y * 8;
    int tid = threadIdx.x;
    int px = tid & 15, ocg = tid >> 4;
    int oc0 = ocg * 8;

    u64 acc[8][4];
    {
        ulonglong2 bp0 = *(const ulonglong2*)&bias[oc0];
        ulonglong2 bp1 = *(const ulonglong2*)&bias[oc0 + 4];
#pragma unroll
        for (int p = 0; p < 8; p++) {
            acc[p][0] = bp0.x; acc[p][1] = bp0.y;
            acc[p][2] = bp1.x; acc[p][3] = bp1.y;
        }
    }

    for (int ci0 = 0; ci0 < 64; ci0 += 8) {
        for (int i = tid; i < 9 * 8 * 64; i += 128) {
            int kk = i >> 9, r = i & 511, cc = r >> 6, oc = r & 63;
            w_sh[kk][cc][oc] = w[((size_t)kk * 64 + ci0 + cc) * 64 + oc];
        }
        for (int i = tid; i < 8 * 10 * 18; i += 128) {
            int cc = i / 180, r = i % 180, yy = r / 18, xx = r % 18;
            int gy = y0 + yy - 1, gx = x0 + xx - 1;
            float v = 0.f;
            if (gy >= 0 && gy < N && gx >= 0 && gx < N) {
                float raw = in[((size_t)(g * 64 + ci0 + cc) * N + gy) * N + gx];
                float sc = abp[(slot * 64 + ci0 + cc) * 2];
                float sf = abp[(slot * 64 + ci0 + cc) * 2 + 1];
                v = fmaxf(sc * raw + sf, 0.f);
            }
            in_sh[cc][yy][xx] = v;
        }
        __syncthreads();
#pragma unroll
        for (int cc = 0; cc < 8; cc++) {
#pragma unroll
            for (int kx = 0; kx < 3; kx++) {
                u64 a[10];
#pragma unroll
                for (int r = 0; r < 10; r++) a[r] = pack_dup(in_sh[cc][r][px + kx]);
#pragma unroll
                for (int ky = 0; ky < 3; ky++) {
                    int kk = ky * 3 + kx;
                    ulonglong2 w01 = *(const ulonglong2*)&w_sh[kk][cc][oc0];
                    ulonglong2 w23 = *(const ulonglong2*)&w_sh[kk][cc][oc0 + 4];
#pragma unroll
                    for (int p = 0; p < 8; p++) {
                        ffma2(acc[p][0], a[p + ky], w01.x);
                        ffma2(acc[p][1], a[p + ky], w01.y);
                        ffma2(acc[p][2], a[p + ky], w23.x);
                        ffma2(acc[p][3], a[p + ky], w23.y);
                    }
                }
            }
        }
        __syncthreads();
    }
    conv_epilogue<N>(acc, g, x0, y0, px, oc0, pooled, part);
}

// ---------------- reduce partials -> BN affine (scale, shift) ----------------
__global__ void __launch_bounds__(256) abreduce_kernel(
    const float* __restrict__ part,
    const float* __restrict__ gamma, const float* __restrict__ beta,
    float* __restrict__ ab, int T, float invCnt)
{
    int slot = blockIdx.x >> 6, c = blockIdx.x & 63;
    int tid = threadIdx.x;
    float s = 0.f, q = 0.f;
    int total = 32 * T;
    for (int i = tid; i < total; i += 256) {
        int b = i / T, t = i % T;
        const float* p = part + ((size_t)((slot * 32 + b) * T + t) * 64 + c) * 2;
        s += p[0]; q += p[1];
    }
    __shared__ float sh1[256], sh2[256];
    sh1[tid] = s; sh2[tid] = q;
    __syncthreads();
    for (int st = 128; st > 0; st >>= 1) {
        if (tid < st) { sh1[tid] += sh1[tid + st]; sh2[tid] += sh2[tid + st]; }
        __syncthreads();
    }
    if (tid == 0) {
        float m = sh1[0] * invCnt;
        float var = sh2[0] * invCnt - m * m;
        float sc = gamma[c] * rsqrtf(var + 1e-3f);
        ab[blockIdx.x * 2]     = sc;
        ab[blockIdx.x * 2 + 1] = beta[c] - m * sc;
    }
}

// ---------------- input projection GEMM: Z[dir][g][128] = relu(a4*raw+b4) @ W + bias ----------------
__global__ void __launch_bounds__(256) gemmz_kernel(
    const float* __restrict__ emb, const float* __restrict__ abp,
    const float* __restrict__ fk, const float* __restrict__ fb,
    const float* __restrict__ bk, const float* __restrict__ bb,
    float* __restrict__ Z)
{
    int gb = blockIdx.x;
    int dir = blockIdx.y;
    const float* W = dir ? bk : fk;
    const float* bias = dir ? bb : fb;
    float* Zo = Z + (size_t)dir * NIMG * 128;

    __shared__ float A_sh[32][33];
    __shared__ __align__(16) float B_sh[32][128];
    int tid = threadIdx.x;
    int jj = tid & 31, gg = tid >> 5;
    float acc[4][4] = {};

    for (int d0 = 0; d0 < 1600; d0 += 32) {
        for (int i = tid; i < 1024; i += 256) {
            int r = i >> 5, dd = i & 31;
            int d = d0 + dd;
            int c = d & 63, pix = d >> 6;
            float raw = emb[(size_t)((gb * 32 + r) * 64 + c) * 25 + pix];
            float sc = abp[(gb * 64 + c) * 2];
            float sf = abp[(gb * 64 + c) * 2 + 1];
            A_sh[r][dd] = fmaxf(sc * raw + sf, 0.f);
        }
        for (int i = tid; i < 4096; i += 256) {
            int dd = i >> 7, j = i & 127;
            B_sh[dd][j] = W[(size_t)(d0 + dd) * 128 + j];
        }
        __syncthreads();
#pragma unroll
        for (int dd = 0; dd < 32; dd++) {
            float4 bv = *(const float4*)&B_sh[dd][jj * 4];
#pragma unroll
            for (int r = 0; r < 4; r++) {
                float a = A_sh[gg * 4 + r][dd];
                acc[r][0] += a * bv.x; acc[r][1] += a * bv.y;
                acc[r][2] += a * bv.z; acc[r][3] += a * bv.w;
            }
        }
        __syncthreads();
    }
#pragma unroll
    for (int r = 0; r < 4; r++) {
#pragma unroll
        for (int c = 0; c < 4; c++) {
            int gi = gb * 32 + gg * 4 + r;
            int j = jj * 4 + c;
            Zo[(size_t)gi * 128 + j] = acc[r][c] + bias[j];
        }
    }
}

// ---------------- LSTM recurrence: one block per (q, dir); batch rows = 21 positions ----------------
__global__ void __launch_bounds__(672) lstm_kernel(
    const float* __restrict__ Z,
    const float* __restrict__ fr, const float* __restrict__ br,
    float* __restrict__ outs)
{
    int q = blockIdx.x, dir = blockIdx.y;
    const float* R = dir ? br : fr;
    const float* Zp = Z + (size_t)dir * NIMG * 128;

    __shared__ float Wh[32][128];
    __shared__ float h_sh[21][32], c_sh[21][32];
    int tid = threadIdx.x;
    for (int i = tid; i < 4096; i += 672) Wh[i >> 7][i & 127] = R[i];
    int p = tid >> 5, j = tid & 31;
    h_sh[p][j] = 0.f; c_sh[p][j] = 0.f;
    __syncthreads();

    int slot = (p < 20) ? p : (20 + q);
    for (int step = 0; step < 32; step++) {
        int t = dir ? (31 - step) : step;
        const float* zr = Zp + (size_t)(slot * 32 + t) * 128;
        float z0 = zr[j], z1 = zr[32 + j], z2 = zr[64 + j], z3 = zr[96 + j];
#pragma unroll
        for (int k = 0; k < 32; k++) {
            float hk = h_sh[p][k];
            z0 += hk * Wh[k][j];
            z1 += hk * Wh[k][32 + j];
            z2 += hk * Wh[k][64 + j];
            z3 += hk * Wh[k][96 + j];
        }
        float ig = 1.f / (1.f + expf(-z0));
        float fg = 1.f / (1.f + expf(-z1));
        float gg = tanhf(z2);
        float og = 1.f / (1.f + expf(-z3));
        float cn = fg * c_sh[p][j] + ig * gg;
        float hn = og * tanhf(cn);
        __syncthreads();
        h_sh[p][j] = hn; c_sh[p][j] = cn;
        outs[(size_t)((q * 21 + p) * 32 + t) * 64 + dir * 32 + j] = hn;
        __syncthreads();
    }
}

// ---------------- attention + softmax + CE + acc ----------------
__global__ void __launch_bounds__(256) final_kernel(
    const float* __restrict__ outs,
    const int* __restrict__ ysup, const int* __restrict__ yqry,
    float* __restrict__ out)
{
    __shared__ float ce_sh[160], eq_sh[160];
    int tid = threadIdx.x;
    if (tid < 160) {
        int q = tid / 32, b = tid % 32;
        const float* qry = outs + (size_t)((q * 21 + 20) * 32 + b) * 64;
        float logit[20];
        for (int s = 0; s < 20; s++) {
            const float* sp = outs + (size_t)((q * 21 + s) * 32 + b) * 64;
            float d = 0.f, n2 = 0.f;
            for (int k = 0; k < 64; k++) { d += qry[k] * sp[k]; n2 += sp[k] * sp[k]; }
            logit[s] = d * rsqrtf(fmaxf(n2, 1e-10f));
        }
        float mx = logit[0];
        for (int s = 1; s < 20; s++) mx = fmaxf(mx, logit[s]);
        float den = 0.f;
        for (int s = 0; s < 20; s++) { logit[s] = expf(logit[s] - mx); den += logit[s]; }
        float invden = 1.f / den;
        float preds[20];
        for (int w = 0; w < 20; w++) preds[w] = 0.f;
        for (int s = 0; s < 20; s++) preds[ysup[b * 20 + s]] += logit[s] * invden;
        int yq = yqry[b * 5 + q];
        float pv = fminf(fmaxf(preds[yq], 1e-7f), 1.f - 1e-7f);
        ce_sh[tid] = -logf(pv);
        int best = 0;
        for (int w = 1; w < 20; w++) if (preds[w] > preds[best]) best = w;
        eq_sh[tid] = (best == yq) ? 1.f : 0.f;
    }
    __syncthreads();
    if (tid < 32) {
        float s = 0.f;
        for (int q = 0; q < 5; q++) s += ce_sh[q * 32 + tid];
        out[tid] = s * 0.2f;
    }
    if (tid == 0) {
        float s = 0.f;
        for (int i = 0; i < 160; i++) s += eq_sh[i];
        out[32] = s / 160.f;
    }
}

// ---------------- launch ----------------
extern "C" void kernel_launch(void* const* d_in, const int* in_sizes, int n_in,
                              void* d_out, int out_size)
{
    (void)in_sizes; (void)n_in; (void)out_size;
    const float* xs   = (const float*)d_in[0];
    const int*   ysup = (const int*)  d_in[1];
    const float* xq   = (const float*)d_in[2];
    const int*   yqry = (const int*)  d_in[3];
    const float* k1 = (const float*)d_in[4];
    const float* b1 = (const float*)d_in[5];
    const float* g1 = (const float*)d_in[6];
    const float* be1 = (const float*)d_in[7];
    const float* k2 = (const float*)d_in[8];
    const float* b2 = (const float*)d_in[9];
    const float* g2 = (const float*)d_in[10];
    const float* be2 = (const float*)d_in[11];
    const float* k3 = (const float*)d_in[12];
    const float* b3 = (const float*)d_in[13];
    const float* g3 = (const float*)d_in[14];
    const float* be3 = (const float*)d_in[15];
    const float* k4 = (const float*)d_in[16];
    const float* b4 = (const float*)d_in[17];
    const float* g4 = (const float*)d_in[18];
    const float* be4 = (const float*)d_in[19];
    const float* fk = (const float*)d_in[20];
    const float* fr = (const float*)d_in[21];
    const float* fb = (const float*)d_in[22];
    const float* bk = (const float*)d_in[23];
    const float* br = (const float*)d_in[24];
    const float* bb = (const float*)d_in[25];

    float *bufA, *bufB, *part, *Z, *outs, *ab;
    cudaGetSymbolAddress((void**)&bufA, g_bufA);
    cudaGetSymbolAddress((void**)&bufB, g_bufB);
    cudaGetSymbolAddress((void**)&part, g_part);
    cudaGetSymbolAddress((void**)&Z,    g_Z);
    cudaGetSymbolAddress((void**)&outs, g_outs);
    cudaGetSymbolAddress((void**)&ab,   g_ab);

    // layer 1: 84 -> pooled raw 42 (bufA), T=66
    convpool1_kernel<<<dim3(6, 11, NIMG), 128>>>(xs, xq, k1, b1, bufA, part);
    abreduce_kernel<<<25 * 64, 256>>>(part, g1, be1, ab, 66, 1.f / (32.f * 84.f * 84.f));
    // layer 2: 42 -> pooled raw 21 (bufB), T=18
    convpool_kernel<42><<<dim3(3, 6, NIMG), 128>>>(bufA, ab, k2, b2, bufB, part);
    abreduce_kernel<<<25 * 64, 256>>>(part, g2, be2, ab, 18, 1.f / (32.f * 42.f * 42.f));
    // layer 3: 21 -> pooled raw 10 (bufA), T=6
    convpool_kernel<21><<<dim3(2, 3, NIMG), 128>>>(bufB, ab, k3, b3, bufA, part);
    abreduce_kernel<<<25 * 64, 256>>>(part, g3, be3, ab, 6, 1.f / (32.f * 21.f * 21.f));
    // layer 4: 10 -> pooled raw 5 (bufB), T=2
    convpool_kernel<10><<<dim3(1, 2, NIMG), 128>>>(bufA, ab, k4, b4, bufB, part);
    abreduce_kernel<<<25 * 64, 256>>>(part, g4, be4, ab, 2, 1.f / (32.f * 10.f * 10.f));

    // LSTM input projections (both directions); BN+ReLU of layer 4 applied on load
    gemmz_kernel<<<dim3(25, 2), 256>>>(bufB, ab, fk, fb, bk, bb, Z);
    // recurrence: one block per (q, dir)
    lstm_kernel<<<dim3(5, 2), 672>>>(Z, fr, br, outs);
    // attention + CE + acc
    final_kernel<<<1, 256>>>(outs, ysup, yqry, (float*)d_out);
}

// round 7
// speedup vs baseline: 1.3577x; 1.0683x over previous
#include <cuda_runtime.h>
#include <cuda_bf16.h>
#include <math.h>
#include <stdint.h>

#define NIMG 800
typedef unsigned long long u64;

// ---------------- scratch ----------------
__device__ float g_pool1[(size_t)NIMG * 1764 * 64];
__device__ float g_raw  [(size_t)NIMG * 1764 * 64];
__device__ float g_pool2[(size_t)NIMG * 441 * 64];
__device__ float g_pool3[(size_t)NIMG * 100 * 64];
__device__ float g_pool4[(size_t)NIMG * 25 * 64];
__device__ float g_part [(size_t)NIMG * 66 * 128];
__device__ float g_Z[2 * NIMG * 128];
__device__ float g_outs[5 * 21 * 32 * 64];
__device__ float g_ab[25 * 64 * 2];

// ---------------- f32x2 helpers (layer-1 SIMT) ----------------
__device__ __forceinline__ u64 pack_dup(float v) {
    u64 r; asm("mov.b64 %0, {%1, %1};" : "=l"(r) : "f"(v)); return r;
}
__device__ __forceinline__ void ffma2(u64& acc, u64 a, u64 b) {
    asm("fma.rn.f32x2 %0, %1, %2, %0;" : "+l"(acc) : "l"(a), "l"(b));
}
__device__ __forceinline__ void unpack2(u64 v, float& lo, float& hi) {
    asm("mov.b64 {%0, %1}, %2;" : "=f"(lo), "=f"(hi) : "l"(v));
}

// ---------------- warp mma ----------------
__device__ __forceinline__ void mma16816(float* d, uint32_t a0, uint32_t a1,
                                         uint32_t a2, uint32_t a3,
                                         uint32_t b0, uint32_t b1) {
    asm volatile(
        "mma.sync.aligned.m16n8k16.row.col.f32.bf16.bf16.f32 "
        "{%0,%1,%2,%3}, {%4,%5,%6,%7}, {%8,%9}, {%0,%1,%2,%3};"
        : "+f"(d[0]), "+f"(d[1]), "+f"(d[2]), "+f"(d[3])
        : "r"(a0), "r"(a1), "r"(a2), "r"(a3), "r"(b0), "r"(b1));
}

// ================= mmaconv: layers 2-4, one block per image, 128 thr =================
// in: pooled prev channels-last [g][NX*NX][64]; raw out channels-last [g][NX*NX][64].
template <int NX, int NT>
__global__ void __launch_bounds__(128) mmaconv_kernel(
    const float* __restrict__ in, const float* __restrict__ abp,
    const float* __restrict__ w, const float* __restrict__ bias,
    float* __restrict__ raw)
{
    constexpr int W = NX + 2, P = W * W, PIX = NX * NX;
    constexpr int ROWS = 2 * W + 132;
    constexpr int SROW = 144;                 // staging & B row stride (conflict-free)
    constexpr int BTAP = 64 * SROW;           // 9216 per tap
    constexpr int OFF_BH = 1024;
    constexpr int OFF_BL = OFF_BH + 9 * BTAP;
    constexpr int OFF_SH = OFF_BL + 9 * BTAP;
    constexpr int OFF_SL = OFF_SH + ROWS * SROW;

    extern __shared__ __align__(16) char smem[];
    int tid = threadIdx.x;
    int g = blockIdx.x, slot = g >> 5;
    float* bias_sh = (float*)(smem + 16);
    float* ab_sh   = (float*)(smem + 304);
    if (tid < 64) bias_sh[tid] = bias[tid];
    if (tid < 128) ab_sh[tid] = abp[slot * 128 + tid];

    // B fill: w[t][ci][oc] -> Bt[t][oc][ci] bf16 hi/lo, row stride SROW
    for (int i = tid; i < 9 * 64 * 64; i += 128) {
        int t = i >> 12, r = i & 4095, ci = r >> 6, oc = r & 63;
        float v = w[i];
        __nv_bfloat16 h = __float2bfloat16(v);
        __nv_bfloat16 l = __float2bfloat16(v - __bfloat162float(h));
        *(__nv_bfloat16*)(smem + OFF_BH + t * BTAP + oc * SROW + ci * 2) = h;
        *(__nv_bfloat16*)(smem + OFF_BL + t * BTAP + oc * SROW + ci * 2) = l;
    }

    int warp = tid >> 5, lane = tid & 31;
    int g_row = lane >> 2, four = lane & 3;
    int mbase = warp * 32;

    for (int tile = 0; tile < NT; tile++) {
        int s0 = tile * 128;
        __syncthreads();   // protect staging vs prev tile's compute
        // ---- stage strip: BN+relu prev, bf16 hi/lo split ----
        for (int i = tid; i < ROWS * 16; i += 128) {
            int r = i >> 4, c4 = (i & 15) * 4;
            int sp = s0 - W - 1 + r;
            float4 v = make_float4(0.f, 0.f, 0.f, 0.f);
            if (sp >= 0 && sp < P) {
                int py = sp / W, px = sp - py * W;
                if (px >= 1 && px <= NX && py >= 1 && py <= NX) {
                    float4 rv = *(const float4*)&in[((size_t)g * PIX + (py - 1) * NX + (px - 1)) * 64 + c4];
                    v.x = fmaxf(fmaf(ab_sh[(c4 + 0) * 2], rv.x, ab_sh[(c4 + 0) * 2 + 1]), 0.f);
                    v.y = fmaxf(fmaf(ab_sh[(c4 + 1) * 2], rv.y, ab_sh[(c4 + 1) * 2 + 1]), 0.f);
                    v.z = fmaxf(fmaf(ab_sh[(c4 + 2) * 2], rv.z, ab_sh[(c4 + 2) * 2 + 1]), 0.f);
                    v.w = fmaxf(fmaf(ab_sh[(c4 + 3) * 2], rv.w, ab_sh[(c4 + 3) * 2 + 1]), 0.f);
                }
            }
            __nv_bfloat162 h01 = __floats2bfloat162_rn(v.x, v.y);
            __nv_bfloat162 h23 = __floats2bfloat162_rn(v.z, v.w);
            __nv_bfloat162 l01 = __floats2bfloat162_rn(v.x - __bfloat162float(h01.x),
                                                       v.y - __bfloat162float(h01.y));
            __nv_bfloat162 l23 = __floats2bfloat162_rn(v.z - __bfloat162float(h23.x),
                                                       v.w - __bfloat162float(h23.y));
            *(uint2*)(smem + OFF_SH + r * SROW + c4 * 2) =
                make_uint2(*(uint32_t*)&h01, *(uint32_t*)&h23);
            *(uint2*)(smem + OFF_SL + r * SROW + c4 * 2) =
                make_uint2(*(uint32_t*)&l01, *(uint32_t*)&l23);
        }
        __syncthreads();

        // ---- compute: D[128][64] via 3 split passes x 9 taps x 4 k-chunks ----
        float d[2][8][4];
#pragma unroll
        for (int mt = 0; mt < 2; mt++)
#pragma unroll
            for (int nt = 0; nt < 8; nt++)
#pragma unroll
                for (int i = 0; i < 4; i++) d[mt][nt][i] = 0.f;

#pragma unroll 1
        for (int pass = 0; pass < 3; pass++) {
            const char* abase = smem + ((pass == 1) ? OFF_SL : OFF_SH);
            const char* bbase = smem + ((pass == 2) ? OFF_BL : OFF_BH);
#pragma unroll 1
            for (int t = 0; t < 9; t++) {
                int rshift = (t / 3) * W + (t % 3);
                const char* bt = bbase + t * BTAP;
#pragma unroll
                for (int kc = 0; kc < 4; kc++) {
                    int cb = kc * 32 + four * 4;   // k0 byte offset
                    uint32_t b0[8], b1[8];
#pragma unroll
                    for (int nt = 0; nt < 8; nt++) {
                        const char* bp = bt + (nt * 8 + g_row) * SROW + cb;
                        b0[nt] = *(const uint32_t*)bp;
                        b1[nt] = *(const uint32_t*)(bp + 16);
                    }
#pragma unroll
                    for (int mt = 0; mt < 2; mt++) {
                        const char* ap = abase + (mbase + rshift + mt * 16 + g_row) * SROW + cb;
                        uint32_t a0 = *(const uint32_t*)ap;
                        uint32_t a1 = *(const uint32_t*)(ap + 8 * SROW);
                        uint32_t a2 = *(const uint32_t*)(ap + 16);
                        uint32_t a3 = *(const uint32_t*)(ap + 8 * SROW + 16);
#pragma unroll
                        for (int nt = 0; nt < 8; nt++)
                            mma16816(d[mt][nt], a0, a1, a2, a3, b0[nt], b1[nt]);
                    }
                }
            }
        }

        // ---- epilogue: add bias, write valid rows channels-last ----
#pragma unroll
        for (int mt = 0; mt < 2; mt++)
#pragma unroll
            for (int rr = 0; rr < 2; rr++) {
                int m = mbase + mt * 16 + g_row + rr * 8;
                int sp = s0 + m;
                if (sp < P) {
                    int py = sp / W, px = sp - py * W;
                    if (px >= 1 && px <= NX && py >= 1 && py <= NX) {
                        float* o = raw + ((size_t)g * PIX + (py - 1) * NX + (px - 1)) * 64;
#pragma unroll
                        for (int nt = 0; nt < 8; nt++) {
                            int oc = nt * 8 + four * 2;
                            float2 v;
                            v.x = d[mt][nt][rr * 2]     + bias_sh[oc];
                            v.y = d[mt][nt][rr * 2 + 1] + bias_sh[oc + 1];
                            *(float2*)(o + oc) = v;
                        }
                    }
                }
            }
    }
}

// ---------------- stats over channels-last raw ----------------
template <int NX, int CH>
__global__ void __launch_bounds__(256) statsCL_kernel(const float* __restrict__ raw,
                                                     float* __restrict__ part)
{
    int slot = blockIdx.x, cy = blockIdx.y;
    int c = threadIdx.x & 63, ln = threadIdx.x >> 6;
    const int E = 32 * NX * NX;
    int e0 = (int)((long)cy * E / CH), e1 = (int)((long)(cy + 1) * E / CH);
    float s = 0.f, q = 0.f;
    const float* base = raw + (size_t)slot * 32 * NX * NX * 64 + c;
    for (int e = e0 + ln; e < e1; e += 4) {
        float v = base[(size_t)e * 64];
        s += v; q += v * v;
    }
    __shared__ float ss[4][64], qq[4][64];
    ss[ln][c] = s; qq[ln][c] = q;
    __syncthreads();
    if (ln == 0) {
        s = ss[0][c] + ss[1][c] + ss[2][c] + ss[3][c];
        q = qq[0][c] + qq[1][c] + qq[2][c] + qq[3][c];
        part[(size_t)(slot * CH + cy) * 128 + c * 2]     = s;
        part[(size_t)(slot * CH + cy) * 128 + c * 2 + 1] = q;
    }
}
template <int CH>
__global__ void __launch_bounds__(64) abfin_kernel(const float* __restrict__ part,
    const float* __restrict__ gamma, const float* __restrict__ beta,
    float* __restrict__ ab, float invCnt)
{
    int slot = blockIdx.x, c = threadIdx.x;
    float s = 0.f, q = 0.f;
    for (int ch = 0; ch < CH; ch++) {
        s += part[(size_t)(slot * CH + ch) * 128 + c * 2];
        q += part[(size_t)(slot * CH + ch) * 128 + c * 2 + 1];
    }
    float mn = s * invCnt;
    float var = q * invCnt - mn * mn;
    float sc = gamma[c] * rsqrtf(var + 1e-3f);
    ab[(slot * 64 + c) * 2] = sc;
    ab[(slot * 64 + c) * 2 + 1] = beta[c] - mn * sc;
}

// ---------------- 2x2 maxpool on channels-last raw (pre-BN, exact) ----------------
template <int NX>
__global__ void __launch_bounds__(256) poolCL_kernel(const float* __restrict__ raw,
                                                    float* __restrict__ out)
{
    constexpr int Np = NX / 2;
    long idx = (long)blockIdx.x * 256 + threadIdx.x;
    if (idx >= (long)NIMG * Np * Np * 64) return;
    int c = (int)(idx & 63); long t = idx >> 6;
    int ox = (int)(t % Np); t /= Np;
    int oy = (int)(t % Np); int g = (int)(t / Np);
    const float* p = raw + ((size_t)g * NX * NX + (2 * oy) * NX + 2 * ox) * 64 + c;
    float v = fmaxf(fmaxf(p[0], p[64]), fmaxf(p[(size_t)NX * 64], p[(size_t)NX * 64 + 64]));
    out[idx] = v;
}

// ---------------- layer 1 SIMT conv + partials + pre-BN pool (channels-last out) ----------------
__device__ __forceinline__ void epi1(
    u64 (&acc)[8][4], int g, int x0, int y0, int px, int oc0,
    float* __restrict__ pooled, float* __restrict__ part)
{
    const int N = 84, Np = 42;
    int T = gridDim.x * gridDim.y;
    int tile = blockIdx.y * gridDim.x + blockIdx.x;
    bool xv = (x0 + px) < N;
    float* partp = part + ((size_t)(g * T + tile) * 64 + oc0) * 2;
    int pooly0 = y0 >> 1, poolx = (x0 + px) >> 1;
#pragma unroll
    for (int j = 0; j < 4; j++) {
        float s0 = 0.f, s1 = 0.f, q0 = 0.f, q1 = 0.f;
        float m0[4], m1[4];
#pragma unroll
        for (int jj = 0; jj < 4; jj++) { m0[jj] = -1e30f; m1[jj] = -1e30f; }
#pragma unroll
        for (int p = 0; p < 8; p++) {
            float v0, v1; unpack2(acc[p][j], v0, v1);
            if (xv && (y0 + p) < N) { s0 += v0; q0 += v0 * v0; s1 += v1; q1 += v1 * v1; }
            m0[p >> 1] = fmaxf(m0[p >> 1], v0);
            m1[p >> 1] = fmaxf(m1[p >> 1], v1);
        }
#pragma unroll
        for (int off = 8; off; off >>= 1) {
            s0 += __shfl_down_sync(~0u, s0, off, 16); s1 += __shfl_down_sync(~0u, s1, off, 16);
            q0 += __shfl_down_sync(~0u, q0, off, 16); q1 += __shfl_down_sync(~0u, q1, off, 16);
        }
        if (px == 0) {
            partp[(2*j)*2] = s0; partp[(2*j)*2+1] = q0;
            partp[(2*j+1)*2] = s1; partp[(2*j+1)*2+1] = q1;
        }
#pragma unroll
        for (int jj = 0; jj < 4; jj++) {
            float o0 = __shfl_xor_sync(~0u, m0[jj], 1);
            float o1 = __shfl_xor_sync(~0u, m1[jj], 1);
            if (!(px & 1)) {
                int py = pooly0 + jj;
                if (py < Np && poolx < Np) {
                    float* o = pooled + ((size_t)g * Np * Np + py * Np + poolx) * 64;
                    o[oc0 + 2*j] = fmaxf(m0[jj], o0);
                    o[oc0 + 2*j + 1] = fmaxf(m1[jj], o1);
                }
            }
        }
    }
}

__global__ void __launch_bounds__(128, 4) convpool1_kernel(
    const float* __restrict__ xs, const float* __restrict__ xq,
    const float* __restrict__ w, const float* __restrict__ bias,
    float* __restrict__ pooled, float* __restrict__ part)
{
    const int N = 84;
    __shared__ __align__(16) float w_sh[9][3][64];
    __shared__ float in_sh[3][10][20];
    int g = blockIdx.z;
    int x0 = blockIdx.x * 16, y0 = blockIdx.y * 8;
    int tid = threadIdx.x;
    int px = tid & 15, oc0 = (tid >> 4) * 8;
    u64 acc[8][4];
    {
        ulonglong2 b0 = *(const ulonglong2*)&bias[oc0];
        ulonglong2 b1 = *(const ulonglong2*)&bias[oc0 + 4];
#pragma unroll
        for (int p = 0; p < 8; p++) { acc[p][0]=b0.x; acc[p][1]=b0.y; acc[p][2]=b1.x; acc[p][3]=b1.y; }
    }
    for (int i = tid; i < 9 * 3 * 64; i += 128) {
        int kk = i / 192, r = i % 192;
        w_sh[kk][r / 64][r % 64] = w[i];
    }
    int b = g & 31, slot = g >> 5;
    const float* src = (slot < 20)
        ? (xs + (size_t)(b * 20 + slot) * 84 * 84 * 3)
        : (xq + (size_t)(b * 5 + (slot - 20)) * 84 * 84 * 3);
    for (int i = tid; i < 3 * 10 * 18; i += 128) {
        int cc = i / 180, r = i % 180, yy = r / 18, xx = r % 18;
        int gy = y0 + yy - 1, gx = x0 + xx - 1;
        float v = 0.f;
        if (gy >= 0 && gy < N && gx >= 0 && gx < N) v = src[(size_t)(gy * 84 + gx) * 3 + cc];
        in_sh[cc][yy][xx] = v;
    }
    __syncthreads();
#pragma unroll
    for (int cc = 0; cc < 3; cc++)
#pragma unroll
        for (int kx = 0; kx < 3; kx++) {
            u64 a[10];
#pragma unroll
            for (int r = 0; r < 10; r++) a[r] = pack_dup(in_sh[cc][r][px + kx]);
#pragma unroll
            for (int ky = 0; ky < 3; ky++) {
                int kk = ky * 3 + kx;
                ulonglong2 w01 = *(const ulonglong2*)&w_sh[kk][cc][oc0];
                ulonglong2 w23 = *(const ulonglong2*)&w_sh[kk][cc][oc0 + 4];
#pragma unroll
                for (int p = 0; p < 8; p++) {
                    ffma2(acc[p][0], a[p + ky], w01.x); ffma2(acc[p][1], a[p + ky], w01.y);
                    ffma2(acc[p][2], a[p + ky], w23.x); ffma2(acc[p][3], a[p + ky], w23.y);
                }
            }
        }
    epi1(acc, g, x0, y0, px, oc0, pooled, part);
}

// L1 partial reduce (tile-indexed layout)
__global__ void __launch_bounds__(256) abreduce_kernel(
    const float* __restrict__ part,
    const float* __restrict__ gamma, const float* __restrict__ beta,
    float* __restrict__ ab, int T, float invCnt)
{
    int slot = blockIdx.x >> 6, c = blockIdx.x & 63;
    int tid = threadIdx.x;
    float s = 0.f, q = 0.f;
    int total = 32 * T;
    for (int i = tid; i < total; i += 256) {
        const float* p = part + ((size_t)(slot * 32 + i / T) * T + i % T) * 128 + c * 2;
        s += p[0]; q += p[1];
    }
    __shared__ float sh1[256], sh2[256];
    sh1[tid] = s; sh2[tid] = q;
    __syncthreads();
    for (int st = 128; st > 0; st >>= 1) {
        if (tid < st) { sh1[tid] += sh1[tid + st]; sh2[tid] += sh2[tid + st]; }
        __syncthreads();
    }
    if (tid == 0) {
        float m = sh1[0] * invCnt;
        float var = sh2[0] * invCnt - m * m;
        float sc = gamma[c] * rsqrtf(var + 1e-3f);
        ab[blockIdx.x * 2] = sc;
        ab[blockIdx.x * 2 + 1] = beta[c] - m * sc;
    }
}

// ---------------- gemmz (pool4 channels-last: d = pix*64 + c directly) ----------------
__global__ void __launch_bounds__(256) gemmz_kernel(
    const float* __restrict__ emb, const float* __restrict__ abp,
    const float* __restrict__ fk, const float* __restrict__ fb,
    const float* __restrict__ bk, const float* __restrict__ bb,
    float* __restrict__ Z)
{
    int gb = blockIdx.x, dir = blockIdx.y;
    const float* W = dir ? bk : fk;
    const float* bias = dir ? bb : fb;
    float* Zo = Z + (size_t)dir * NIMG * 128;
    __shared__ float A_sh[32][33];
    __shared__ __align__(16) float B_sh[32][128];
    int tid = threadIdx.x, jj = tid & 31, gg = tid >> 5;
    float acc[4][4] = {};
    for (int d0 = 0; d0 < 1600; d0 += 32) {
        for (int i = tid; i < 1024; i += 256) {
            int r = i >> 5, dd = i & 31, d = d0 + dd, c = d & 63;
            float raw = emb[(size_t)(gb * 32 + r) * 1600 + d];
            A_sh[r][dd] = fmaxf(fmaf(abp[(gb * 64 + c) * 2], raw, abp[(gb * 64 + c) * 2 + 1]), 0.f);
        }
        for (int i = tid; i < 4096; i += 256)
            B_sh[i >> 7][i & 127] = W[(size_t)(d0 + (i >> 7)) * 128 + (i & 127)];
        __syncthreads();
#pragma unroll
        for (int dd = 0; dd < 32; dd++) {
            float4 bv = *(const float4*)&B_sh[dd][jj * 4];
#pragma unroll
            for (int r = 0; r < 4; r++) {
                float a = A_sh[gg * 4 + r][dd];
                acc[r][0] += a * bv.x; acc[r][1] += a * bv.y;
                acc[r][2] += a * bv.z; acc[r][3] += a * bv.w;
            }
        }
        __syncthreads();
    }
#pragma unroll
    for (int r = 0; r < 4; r++)
#pragma unroll
        for (int c = 0; c < 4; c++)
            Zo[(size_t)(gb * 32 + gg * 4 + r) * 128 + jj * 4 + c] = acc[r][c] + bias[jj * 4 + c];
}

// ---------------- LSTM ----------------
__global__ void __launch_bounds__(672) lstm_kernel(
    const float* __restrict__ Z,
    const float* __restrict__ fr, const float* __restrict__ br,
    float* __restrict__ outs)
{
    int q = blockIdx.x, dir = blockIdx.y;
    const float* R = dir ? br : fr;
    const float* Zp = Z + (size_t)dir * NIMG * 128;
    __shared__ float Wh[32][128];
    __shared__ float h_sh[21][32], c_sh[21][32];
    int tid = threadIdx.x;
    for (int i = tid; i < 4096; i += 672) Wh[i >> 7][i & 127] = R[i];
    int p = tid >> 5, j = tid & 31;
    h_sh[p][j] = 0.f; c_sh[p][j] = 0.f;
    __syncthreads();
    int slot = (p < 20) ? p : (20 + q);
    for (int step = 0; step < 32; step++) {
        int t = dir ? (31 - step) : step;
        const float* zr = Zp + (size_t)(slot * 32 + t) * 128;
        float z0 = zr[j], z1 = zr[32 + j], z2 = zr[64 + j], z3 = zr[96 + j];
#pragma unroll
        for (int k = 0; k < 32; k++) {
            float hk = h_sh[p][k];
            z0 += hk * Wh[k][j]; z1 += hk * Wh[k][32 + j];
            z2 += hk * Wh[k][64 + j]; z3 += hk * Wh[k][96 + j];
        }
        float ig = 1.f / (1.f + expf(-z0)), fg = 1.f / (1.f + expf(-z1));
        float gg = tanhf(z2), og = 1.f / (1.f + expf(-z3));
        float cn = fg * c_sh[p][j] + ig * gg;
        float hn = og * tanhf(cn);
        __syncthreads();
        h_sh[p][j] = hn; c_sh[p][j] = cn;
        outs[(size_t)((q * 21 + p) * 32 + t) * 64 + dir * 32 + j] = hn;
        __syncthreads();
    }
}

// ---------------- attention + CE + acc ----------------
__global__ void __launch_bounds__(256) final_kernel(
    const float* __restrict__ outs,
    const int* __restrict__ ysup, const int* __restrict__ yqry,
    float* __restrict__ out)
{
    __shared__ float ce_sh[160], eq_sh[160];
    int tid = threadIdx.x;
    if (tid < 160) {
        int q = tid / 32, b = tid % 32;
        const float* qry = outs + (size_t)((q * 21 + 20) * 32 + b) * 64;
        float logit[20];
        for (int s = 0; s < 20; s++) {
            const float* sp = outs + (size_t)((q * 21 + s) * 32 + b) * 64;
            float d = 0.f, n2 = 0.f;
            for (int k = 0; k < 64; k++) { d += qry[k] * sp[k]; n2 += sp[k] * sp[k]; }
            logit[s] = d * rsqrtf(fmaxf(n2, 1e-10f));
        }
        float mx = logit[0];
        for (int s = 1; s < 20; s++) mx = fmaxf(mx, logit[s]);
        float den = 0.f;
        for (int s = 0; s < 20; s++) { logit[s] = expf(logit[s] - mx); den += logit[s]; }
        float invden = 1.f / den;
        float preds[20];
        for (int wq = 0; wq < 20; wq++) preds[wq] = 0.f;
        for (int s = 0; s < 20; s++) preds[ysup[b * 20 + s]] += logit[s] * invden;
        int yq = yqry[b * 5 + q];
        float pv = fminf(fmaxf(preds[yq], 1e-7f), 1.f - 1e-7f);
        ce_sh[tid] = -logf(pv);
        int best = 0;
        for (int wq = 1; wq < 20; wq++) if (preds[wq] > preds[best]) best = wq;
        eq_sh[tid] = (best == yq) ? 1.f : 0.f;
    }
    __syncthreads();
    if (tid < 32) {
        float s = 0.f;
        for (int q = 0; q < 5; q++) s += ce_sh[q * 32 + tid];
        out[tid] = s * 0.2f;
    }
    if (tid == 0) {
        float s = 0.f;
        for (int i = 0; i < 160; i++) s += eq_sh[i];
        out[32] = s / 160.f;
    }
}

// ---------------- launch ----------------
extern "C" void kernel_launch(void* const* d_in, const int* in_sizes, int n_in,
                              void* d_out, int out_size)
{
    (void)in_sizes; (void)n_in; (void)out_size;
    const float* xs = (const float*)d_in[0];
    const int* ysup = (const int*)d_in[1];
    const float* xq = (const float*)d_in[2];
    const int* yqry = (const int*)d_in[3];
    const float *k1=(const float*)d_in[4],  *b1=(const float*)d_in[5],  *g1=(const float*)d_in[6],  *be1=(const float*)d_in[7];
    const float *k2=(const float*)d_in[8],  *b2=(const float*)d_in[9],  *g2=(const float*)d_in[10], *be2=(const float*)d_in[11];
    const float *k3=(const float*)d_in[12], *b3=(const float*)d_in[13], *g3=(const float*)d_in[14], *be3=(const float*)d_in[15];
    const float *k4=(const float*)d_in[16], *b4=(const float*)d_in[17], *g4=(const float*)d_in[18], *be4=(const float*)d_in[19];
    const float *fk=(const float*)d_in[20], *fr=(const float*)d_in[21], *fb=(const float*)d_in[22];
    const float *bk=(const float*)d_in[23], *br=(const float*)d_in[24], *bb=(const float*)d_in[25];

    float *pool1, *raw, *pool2, *pool3, *pool4, *part, *Z, *outs, *ab;
    cudaGetSymbolAddress((void**)&pool1, g_pool1);
    cudaGetSymbolAddress((void**)&raw, g_raw);
    cudaGetSymbolAddress((void**)&pool2, g_pool2);
    cudaGetSymbolAddress((void**)&pool3, g_pool3);
    cudaGetSymbolAddress((void**)&pool4, g_pool4);
    cudaGetSymbolAddress((void**)&part, g_part);
    cudaGetSymbolAddress((void**)&Z, g_Z);
    cudaGetSymbolAddress((void**)&outs, g_outs);
    cudaGetSymbolAddress((void**)&ab, g_ab);

    // smem: 1024 hdr + 2 * 9*64*144 (B hi/lo) + 2 * ROWS*144 (staging hi/lo)
    const int SM42 = 1024 + 2 * 9 * 64 * 144 + 2 * (2 * 44 + 132) * 144;  // 230272
    const int SM21 = 1024 + 2 * 9 * 64 * 144 + 2 * (2 * 23 + 132) * 144;  // 218176
    const int SM10 = 1024 + 2 * 9 * 64 * 144 + 2 * (2 * 12 + 132) * 144;  // 211840
    cudaFuncSetAttribute(mmaconv_kernel<42,16>, cudaFuncAttributeMaxDynamicSharedMemorySize, SM42);
    cudaFuncSetAttribute(mmaconv_kernel<21,5>,  cudaFuncAttributeMaxDynamicSharedMemorySize, SM21);
    cudaFuncSetAttribute(mmaconv_kernel<10,2>,  cudaFuncAttributeMaxDynamicSharedMemorySize, SM10);

    // L1: SIMT conv 84 -> pooled CL 42 + stats partials
    convpool1_kernel<<<dim3(6, 11, NIMG), 128>>>(xs, xq, k1, b1, pool1, part);
    abreduce_kernel<<<25 * 64, 256>>>(part, g1, be1, ab, 66, 1.f / (32.f * 84.f * 84.f));
    // L2: mma conv on 42
    mmaconv_kernel<42,16><<<NIMG, 128, SM42>>>(pool1, ab, k2, b2, raw);
    statsCL_kernel<42,12><<<dim3(25, 12), 256>>>(raw, part);
    poolCL_kernel<42><<<(NIMG*441*64 + 255)/256, 256>>>(raw, pool2);
    abfin_kernel<12><<<25, 64>>>(part, g2, be2, ab, 1.f / (32.f * 1764.f));
    // L3: mma conv on 21
    mmaconv_kernel<21,5><<<NIMG, 128, SM21>>>(pool2, ab, k3, b3, raw);
    statsCL_kernel<21,4><<<dim3(25, 4), 256>>>(raw, part);
    poolCL_kernel<21><<<(NIMG*100*64 + 255)/256, 256>>>(raw, pool3);
    abfin_kernel<4><<<25, 64>>>(part, g3, be3, ab, 1.f / (32.f * 441.f));
    // L4: mma conv on 10
    mmaconv_kernel<10,2><<<NIMG, 128, SM10>>>(pool3, ab, k4, b4, raw);
    statsCL_kernel<10,1><<<dim3(25, 1), 256>>>(raw, part);
    poolCL_kernel<10><<<(NIMG*25*64 + 255)/256, 256>>>(raw, pool4);
    abfin_kernel<1><<<25, 64>>>(part, g4, be4, ab, 1.f / (32.f * 100.f));

    gemmz_kernel<<<dim3(25, 2), 256>>>(pool4, ab, fk, fb, bk, bb, Z);
    lstm_kernel<<<dim3(5, 2), 672>>>(Z, fr, br, outs);
    final_kernel<<<1, 256>>>(outs, ysup, yqry, (float*)d_out);
}

// round 8
// speedup vs baseline: 1.4533x; 1.0704x over previous
#include <cuda_runtime.h>
#include <cuda_bf16.h>
#include <math.h>
#include <stdint.h>

#define NIMG 800
typedef unsigned long long u64;

// ---------------- scratch ----------------
__device__ float g_pool1[(size_t)NIMG * 1764 * 64];
__device__ float g_raw  [(size_t)NIMG * 1764 * 64];
__device__ float g_pool2[(size_t)NIMG * 441 * 64];
__device__ float g_pool3[(size_t)NIMG * 100 * 64];
__device__ float g_pool4[(size_t)NIMG * 25 * 64];
__device__ float g_part [(size_t)NIMG * 66 * 128];   // L1 tile partials; L2-4: [g][128]
__device__ float g_Z[2 * NIMG * 128];
__device__ float g_outs[5 * 21 * 32 * 64];
__device__ float g_ab[25 * 64 * 2];

// ---------------- f32x2 helpers (layer-1 SIMT) ----------------
__device__ __forceinline__ u64 pack_dup(float v) {
    u64 r; asm("mov.b64 %0, {%1, %1};" : "=l"(r) : "f"(v)); return r;
}
__device__ __forceinline__ void ffma2(u64& acc, u64 a, u64 b) {
    asm("fma.rn.f32x2 %0, %1, %2, %0;" : "+l"(acc) : "l"(a), "l"(b));
}
__device__ __forceinline__ void unpack2(u64 v, float& lo, float& hi) {
    asm("mov.b64 {%0, %1}, %2;" : "=f"(lo), "=f"(hi) : "l"(v));
}

// ---------------- warp mma ----------------
__device__ __forceinline__ void mma16816(float* d, uint32_t a0, uint32_t a1,
                                         uint32_t a2, uint32_t a3,
                                         uint32_t b0, uint32_t b1) {
    asm volatile(
        "mma.sync.aligned.m16n8k16.row.col.f32.bf16.bf16.f32 "
        "{%0,%1,%2,%3}, {%4,%5,%6,%7}, {%8,%9}, {%0,%1,%2,%3};"
        : "+f"(d[0]), "+f"(d[1]), "+f"(d[2]), "+f"(d[3])
        : "r"(a0), "r"(a1), "r"(a2), "r"(a3), "r"(b0), "r"(b1));
}

// ================= mmaconv: layers 2-4, one block per image, 256 thr =================
// in: pooled prev channels-last [g][NX*NX][64]; raw out channels-last; stats fused -> part[g][128].
template <int NX, int NT>
__global__ void __launch_bounds__(256) mmaconv_kernel(
    const float* __restrict__ in, const float* __restrict__ abp,
    const float* __restrict__ w, const float* __restrict__ bias,
    float* __restrict__ raw, float* __restrict__ part)
{
    constexpr int W = NX + 2, P = W * W, PIX = NX * NX;
    constexpr int ROWS = 2 * W + 132;
    constexpr int SROW = 144;                 // staging & B row stride (conflict-light)
    constexpr int BTAP = 64 * SROW;           // 9216 per tap
    constexpr int OFF_BH = 1024;
    constexpr int OFF_BL = OFF_BH + 9 * BTAP;
    constexpr int OFF_SH = OFF_BL + 9 * BTAP;
    constexpr int OFF_SL = OFF_SH + ROWS * SROW;

    extern __shared__ __align__(16) char smem[];
    int tid = threadIdx.x;
    int g = blockIdx.x, slot = g >> 5;
    float* bias_sh = (float*)(smem + 16);
    float* ab_sh   = (float*)(smem + 304);
    if (tid < 64) bias_sh[tid] = bias[tid];
    if (tid < 128) ab_sh[tid] = abp[slot * 128 + tid];

    // B fill: w[t][ci][oc] -> Bt[t][oc][ci] bf16 hi/lo, row stride SROW
    for (int i = tid; i < 9 * 64 * 64; i += 256) {
        int t = i >> 12, r = i & 4095, ci = r >> 6, oc = r & 63;
        float v = w[i];
        __nv_bfloat16 h = __float2bfloat16(v);
        __nv_bfloat16 l = __float2bfloat16(v - __bfloat162float(h));
        *(__nv_bfloat16*)(smem + OFF_BH + t * BTAP + oc * SROW + ci * 2) = h;
        *(__nv_bfloat16*)(smem + OFF_BL + t * BTAP + oc * SROW + ci * 2) = l;
    }

    int warp = tid >> 5, lane = tid & 31;
    int g_row = lane >> 2, four = lane & 3;
    int mbase = warp * 16;                    // 8 warps x m16

    float ps[8][2], qs[8][2];
#pragma unroll
    for (int nt = 0; nt < 8; nt++) { ps[nt][0]=0.f; ps[nt][1]=0.f; qs[nt][0]=0.f; qs[nt][1]=0.f; }

    for (int tile = 0; tile < NT; tile++) {
        int s0 = tile * 128;
        __syncthreads();   // protect staging vs prev tile's compute
        // ---- stage strip: BN+relu prev, bf16 hi/lo split ----
        for (int i = tid; i < ROWS * 16; i += 256) {
            int r = i >> 4, c4 = (i & 15) * 4;
            int sp = s0 - W - 1 + r;
            float4 v = make_float4(0.f, 0.f, 0.f, 0.f);
            if (sp >= 0 && sp < P) {
                int py = sp / W, px = sp - py * W;
                if (px >= 1 && px <= NX && py >= 1 && py <= NX) {
                    float4 rv = *(const float4*)&in[((size_t)g * PIX + (py - 1) * NX + (px - 1)) * 64 + c4];
                    v.x = fmaxf(fmaf(ab_sh[(c4 + 0) * 2], rv.x, ab_sh[(c4 + 0) * 2 + 1]), 0.f);
                    v.y = fmaxf(fmaf(ab_sh[(c4 + 1) * 2], rv.y, ab_sh[(c4 + 1) * 2 + 1]), 0.f);
                    v.z = fmaxf(fmaf(ab_sh[(c4 + 2) * 2], rv.z, ab_sh[(c4 + 2) * 2 + 1]), 0.f);
                    v.w = fmaxf(fmaf(ab_sh[(c4 + 3) * 2], rv.w, ab_sh[(c4 + 3) * 2 + 1]), 0.f);
                }
            }
            __nv_bfloat162 h01 = __floats2bfloat162_rn(v.x, v.y);
            __nv_bfloat162 h23 = __floats2bfloat162_rn(v.z, v.w);
            __nv_bfloat162 l01 = __floats2bfloat162_rn(v.x - __bfloat162float(h01.x),
                                                       v.y - __bfloat162float(h01.y));
            __nv_bfloat162 l23 = __floats2bfloat162_rn(v.z - __bfloat162float(h23.x),
                                                       v.w - __bfloat162float(h23.y));
            *(uint2*)(smem + OFF_SH + r * SROW + c4 * 2) =
                make_uint2(*(uint32_t*)&h01, *(uint32_t*)&h23);
            *(uint2*)(smem + OFF_SL + r * SROW + c4 * 2) =
                make_uint2(*(uint32_t*)&l01, *(uint32_t*)&l23);
        }
        __syncthreads();

        // ---- compute: warp covers rows [mbase, mbase+16) x 64 oc ----
        float d[8][4];
#pragma unroll
        for (int nt = 0; nt < 8; nt++)
#pragma unroll
            for (int i = 0; i < 4; i++) d[nt][i] = 0.f;

#pragma unroll 1
        for (int pass = 0; pass < 3; pass++) {
            const char* abase = smem + ((pass == 1) ? OFF_SL : OFF_SH);
            const char* bbase = smem + ((pass == 2) ? OFF_BL : OFF_BH);
#pragma unroll 1
            for (int t = 0; t < 9; t++) {
                int rshift = (t / 3) * W + (t % 3);
                const char* bt = bbase + t * BTAP;
#pragma unroll
                for (int kc = 0; kc < 4; kc++) {
                    int cb = kc * 32 + four * 4;   // k0 byte offset
                    const char* ap = abase + (mbase + rshift + g_row) * SROW + cb;
                    uint32_t a0 = *(const uint32_t*)ap;
                    uint32_t a1 = *(const uint32_t*)(ap + 8 * SROW);
                    uint32_t a2 = *(const uint32_t*)(ap + 16);
                    uint32_t a3 = *(const uint32_t*)(ap + 8 * SROW + 16);
#pragma unroll
                    for (int nt = 0; nt < 8; nt++) {
                        const char* bp = bt + (nt * 8 + g_row) * SROW + cb;
                        uint32_t b0 = *(const uint32_t*)bp;
                        uint32_t b1 = *(const uint32_t*)(bp + 16);
                        mma16816(d[nt], a0, a1, a2, a3, b0, b1);
                    }
                }
            }
        }

        // ---- epilogue: bias, write valid rows channels-last, fused stats ----
#pragma unroll
        for (int rr = 0; rr < 2; rr++) {
            int m = mbase + g_row + rr * 8;
            int sp = s0 + m;
            bool ok = false;
            float* o = 0;
            if (sp < P) {
                int py = sp / W, px = sp - py * W;
                if (px >= 1 && px <= NX && py >= 1 && py <= NX) {
                    ok = true;
                    o = raw + ((size_t)g * PIX + (py - 1) * NX + (px - 1)) * 64;
                }
            }
#pragma unroll
            for (int nt = 0; nt < 8; nt++) {
                int oc = nt * 8 + four * 2;
                float vx = d[nt][rr * 2]     + bias_sh[oc];
                float vy = d[nt][rr * 2 + 1] + bias_sh[oc + 1];
                if (ok) {
                    *(float2*)(o + oc) = make_float2(vx, vy);
                    ps[nt][0] += vx; qs[nt][0] += vx * vx;
                    ps[nt][1] += vy; qs[nt][1] += vy * vy;
                }
            }
        }
    }

    // ---- stats reduction: lanes (over g_row), then warps, -> part[g][128] ----
#pragma unroll
    for (int nt = 0; nt < 8; nt++)
#pragma unroll
        for (int j = 0; j < 2; j++) {
#pragma unroll
            for (int off = 16; off >= 4; off >>= 1) {
                ps[nt][j] += __shfl_down_sync(~0u, ps[nt][j], off);
                qs[nt][j] += __shfl_down_sync(~0u, qs[nt][j], off);
            }
        }
    __syncthreads();   // staging region no longer needed
    float* wst = (float*)(smem + OFF_SH);
    if (lane < 4) {
#pragma unroll
        for (int nt = 0; nt < 8; nt++)
#pragma unroll
            for (int j = 0; j < 2; j++) {
                int oc = nt * 8 + lane * 2 + j;
                wst[warp * 128 + oc]      = ps[nt][j];
                wst[warp * 128 + 64 + oc] = qs[nt][j];
            }
    }
    __syncthreads();
    if (tid < 128) {
        float s = 0.f;
#pragma unroll
        for (int wi = 0; wi < 8; wi++) s += wst[wi * 128 + tid];
        part[(size_t)g * 128 + tid] = s;
    }
}

// ---------------- per-slot BN affine from per-image partials [g][128] ----------------
__global__ void __launch_bounds__(64) abfin2_kernel(const float* __restrict__ part,
    const float* __restrict__ gamma, const float* __restrict__ beta,
    float* __restrict__ ab, float invCnt)
{
    int slot = blockIdx.x, c = threadIdx.x;
    float s = 0.f, q = 0.f;
    for (int b = 0; b < 32; b++) {
        s += part[(size_t)(slot * 32 + b) * 128 + c];
        q += part[(size_t)(slot * 32 + b) * 128 + 64 + c];
    }
    float mn = s * invCnt;
    float var = q * invCnt - mn * mn;
    float sc = gamma[c] * rsqrtf(var + 1e-3f);
    ab[(slot * 64 + c) * 2] = sc;
    ab[(slot * 64 + c) * 2 + 1] = beta[c] - mn * sc;
}

// ---------------- 2x2 maxpool on channels-last raw (pre-BN, exact) ----------------
template <int NX>
__global__ void __launch_bounds__(256) poolCL_kernel(const float* __restrict__ raw,
                                                    float* __restrict__ out)
{
    constexpr int Np = NX / 2;
    long idx = (long)blockIdx.x * 256 + threadIdx.x;
    if (idx >= (long)NIMG * Np * Np * 64) return;
    int c = (int)(idx & 63); long t = idx >> 6;
    int ox = (int)(t % Np); t /= Np;
    int oy = (int)(t % Np); int g = (int)(t / Np);
    const float* p = raw + ((size_t)g * NX * NX + (2 * oy) * NX + 2 * ox) * 64 + c;
    float v = fmaxf(fmaxf(p[0], p[64]), fmaxf(p[(size_t)NX * 64], p[(size_t)NX * 64 + 64]));
    out[idx] = v;
}

// ---------------- layer 1 SIMT conv + partials + pre-BN pool (channels-last out) ----------------
__device__ __forceinline__ void epi1(
    u64 (&acc)[8][4], int g, int x0, int y0, int px, int oc0,
    float* __restrict__ pooled, float* __restrict__ part)
{
    const int N = 84, Np = 42;
    int T = gridDim.x * gridDim.y;
    int tile = blockIdx.y * gridDim.x + blockIdx.x;
    bool xv = (x0 + px) < N;
    float* partp = part + ((size_t)(g * T + tile) * 64 + oc0) * 2;
    int pooly0 = y0 >> 1, poolx = (x0 + px) >> 1;
#pragma unroll
    for (int j = 0; j < 4; j++) {
        float s0 = 0.f, s1 = 0.f, q0 = 0.f, q1 = 0.f;
        float m0[4], m1[4];
#pragma unroll
        for (int jj = 0; jj < 4; jj++) { m0[jj] = -1e30f; m1[jj] = -1e30f; }
#pragma unroll
        for (int p = 0; p < 8; p++) {
            float v0, v1; unpack2(acc[p][j], v0, v1);
            if (xv && (y0 + p) < N) { s0 += v0; q0 += v0 * v0; s1 += v1; q1 += v1 * v1; }
            m0[p >> 1] = fmaxf(m0[p >> 1], v0);
            m1[p >> 1] = fmaxf(m1[p >> 1], v1);
        }
#pragma unroll
        for (int off = 8; off; off >>= 1) {
            s0 += __shfl_down_sync(~0u, s0, off, 16); s1 += __shfl_down_sync(~0u, s1, off, 16);
            q0 += __shfl_down_sync(~0u, q0, off, 16); q1 += __shfl_down_sync(~0u, q1, off, 16);
        }
        if (px == 0) {
            partp[(2*j)*2] = s0; partp[(2*j)*2+1] = q0;
            partp[(2*j+1)*2] = s1; partp[(2*j+1)*2+1] = q1;
        }
#pragma unroll
        for (int jj = 0; jj < 4; jj++) {
            float o0 = __shfl_xor_sync(~0u, m0[jj], 1);
            float o1 = __shfl_xor_sync(~0u, m1[jj], 1);
            if (!(px & 1)) {
                int py = pooly0 + jj;
                if (py < Np && poolx < Np) {
                    float* o = pooled + ((size_t)g * Np * Np + py * Np + poolx) * 64;
                    o[oc0 + 2*j] = fmaxf(m0[jj], o0);
                    o[oc0 + 2*j + 1] = fmaxf(m1[jj], o1);
                }
            }
        }
    }
}

__global__ void __launch_bounds__(128, 4) convpool1_kernel(
    const float* __restrict__ xs, const float* __restrict__ xq,
    const float* __restrict__ w, const float* __restrict__ bias,
    float* __restrict__ pooled, float* __restrict__ part)
{
    const int N = 84;
    __shared__ __align__(16) float w_sh[9][3][64];
    __shared__ float in_sh[3][10][20];
    int g = blockIdx.z;
    int x0 = blockIdx.x * 16, y0 = blockIdx.y * 8;
    int tid = threadIdx.x;
    int px = tid & 15, oc0 = (tid >> 4) * 8;
    u64 acc[8][4];
    {
        ulonglong2 b0 = *(const ulonglong2*)&bias[oc0];
        ulonglong2 b1 = *(const ulonglong2*)&bias[oc0 + 4];
#pragma unroll
        for (int p = 0; p < 8; p++) { acc[p][0]=b0.x; acc[p][1]=b0.y; acc[p][2]=b1.x; acc[p][3]=b1.y; }
    }
    for (int i = tid; i < 9 * 3 * 64; i += 128) {
        int kk = i / 192, r = i % 192;
        w_sh[kk][r / 64][r % 64] = w[i];
    }
    int b = g & 31, slot = g >> 5;
    const float* src = (slot < 20)
        ? (xs + (size_t)(b * 20 + slot) * 84 * 84 * 3)
        : (xq + (size_t)(b * 5 + (slot - 20)) * 84 * 84 * 3);
    for (int i = tid; i < 3 * 10 * 18; i += 128) {
        int cc = i / 180, r = i % 180, yy = r / 18, xx = r % 18;
        int gy = y0 + yy - 1, gx = x0 + xx - 1;
        float v = 0.f;
        if (gy >= 0 && gy < N && gx >= 0 && gx < N) v = src[(size_t)(gy * 84 + gx) * 3 + cc];
        in_sh[cc][yy][xx] = v;
    }
    __syncthreads();
#pragma unroll
    for (int cc = 0; cc < 3; cc++)
#pragma unroll
        for (int kx = 0; kx < 3; kx++) {
            u64 a[10];
#pragma unroll
            for (int r = 0; r < 10; r++) a[r] = pack_dup(in_sh[cc][r][px + kx]);
#pragma unroll
            for (int ky = 0; ky < 3; ky++) {
                int kk = ky * 3 + kx;
                ulonglong2 w01 = *(const ulonglong2*)&w_sh[kk][cc][oc0];
                ulonglong2 w23 = *(const ulonglong2*)&w_sh[kk][cc][oc0 + 4];
#pragma unroll
                for (int p = 0; p < 8; p++) {
                    ffma2(acc[p][0], a[p + ky], w01.x); ffma2(acc[p][1], a[p + ky], w01.y);
                    ffma2(acc[p][2], a[p + ky], w23.x); ffma2(acc[p][3], a[p + ky], w23.y);
                }
            }
        }
    epi1(acc, g, x0, y0, px, oc0, pooled, part);
}

// L1 partial reduce (tile-indexed layout)
__global__ void __launch_bounds__(256) abreduce_kernel(
    const float* __restrict__ part,
    const float* __restrict__ gamma, const float* __restrict__ beta,
    float* __restrict__ ab, int T, float invCnt)
{
    int slot = blockIdx.x >> 6, c = blockIdx.x & 63;
    int tid = threadIdx.x;
    float s = 0.f, q = 0.f;
    int total = 32 * T;
    for (int i = tid; i < total; i += 256) {
        const float* p = part + ((size_t)(slot * 32 + i / T) * T + i % T) * 128 + c * 2;
        s += p[0]; q += p[1];
    }
    __shared__ float sh1[256], sh2[256];
    sh1[tid] = s; sh2[tid] = q;
    __syncthreads();
    for (int st = 128; st > 0; st >>= 1) {
        if (tid < st) { sh1[tid] += sh1[tid + st]; sh2[tid] += sh2[tid + st]; }
        __syncthreads();
    }
    if (tid == 0) {
        float m = sh1[0] * invCnt;
        float var = sh2[0] * invCnt - m * m;
        float sc = gamma[c] * rsqrtf(var + 1e-3f);
        ab[blockIdx.x * 2] = sc;
        ab[blockIdx.x * 2 + 1] = beta[c] - m * sc;
    }
}

// ---------------- gemmz (pool4 channels-last: d = pix*64 + c directly) ----------------
__global__ void __launch_bounds__(256) gemmz_kernel(
    const float* __restrict__ emb, const float* __restrict__ abp,
    const float* __restrict__ fk, const float* __restrict__ fb,
    const float* __restrict__ bk, const float* __restrict__ bb,
    float* __restrict__ Z)
{
    int gb = blockIdx.x, dir = blockIdx.y;
    const float* W = dir ? bk : fk;
    const float* bias = dir ? bb : fb;
    float* Zo = Z + (size_t)dir * NIMG * 128;
    __shared__ float A_sh[32][33];
    __shared__ __align__(16) float B_sh[32][128];
    int tid = threadIdx.x, jj = tid & 31, gg = tid >> 5;
    float acc[4][4] = {};
    for (int d0 = 0; d0 < 1600; d0 += 32) {
        for (int i = tid; i < 1024; i += 256) {
            int r = i >> 5, dd = i & 31, d = d0 + dd, c = d & 63;
            float raw = emb[(size_t)(gb * 32 + r) * 1600 + d];
            A_sh[r][dd] = fmaxf(fmaf(abp[(gb * 64 + c) * 2], raw, abp[(gb * 64 + c) * 2 + 1]), 0.f);
        }
        for (int i = tid; i < 4096; i += 256)
            B_sh[i >> 7][i & 127] = W[(size_t)(d0 + (i >> 7)) * 128 + (i & 127)];
        __syncthreads();
#pragma unroll
        for (int dd = 0; dd < 32; dd++) {
            float4 bv = *(const float4*)&B_sh[dd][jj * 4];
#pragma unroll
            for (int r = 0; r < 4; r++) {
                float a = A_sh[gg * 4 + r][dd];
                acc[r][0] += a * bv.x; acc[r][1] += a * bv.y;
                acc[r][2] += a * bv.z; acc[r][3] += a * bv.w;
            }
        }
        __syncthreads();
    }
#pragma unroll
    for (int r = 0; r < 4; r++)
#pragma unroll
        for (int c = 0; c < 4; c++)
            Zo[(size_t)(gb * 32 + gg * 4 + r) * 128 + jj * 4 + c] = acc[r][c] + bias[jj * 4 + c];
}

// ---------------- LSTM ----------------
__global__ void __launch_bounds__(672) lstm_kernel(
    const float* __restrict__ Z,
    const float* __restrict__ fr, const float* __restrict__ br,
    float* __restrict__ outs)
{
    int q = blockIdx.x, dir = blockIdx.y;
    const float* R = dir ? br : fr;
    const float* Zp = Z + (size_t)dir * NIMG * 128;
    __shared__ float Wh[32][128];
    __shared__ float h_sh[21][32], c_sh[21][32];
    int tid = threadIdx.x;
    for (int i = tid; i < 4096; i += 672) Wh[i >> 7][i & 127] = R[i];
    int p = tid >> 5, j = tid & 31;
    h_sh[p][j] = 0.f; c_sh[p][j] = 0.f;
    __syncthreads();
    int slot = (p < 20) ? p : (20 + q);
    for (int step = 0; step < 32; step++) {
        int t = dir ? (31 - step) : step;
        const float* zr = Zp + (size_t)(slot * 32 + t) * 128;
        float z0 = zr[j], z1 = zr[32 + j], z2 = zr[64 + j], z3 = zr[96 + j];
#pragma unroll
        for (int k = 0; k < 32; k++) {
            float hk = h_sh[p][k];
            z0 += hk * Wh[k][j]; z1 += hk * Wh[k][32 + j];
            z2 += hk * Wh[k][64 + j]; z3 += hk * Wh[k][96 + j];
        }
        float ig = 1.f / (1.f + expf(-z0)), fg = 1.f / (1.f + expf(-z1));
        float gg = tanhf(z2), og = 1.f / (1.f + expf(-z3));
        float cn = fg * c_sh[p][j] + ig * gg;
        float hn = og * tanhf(cn);
        __syncthreads();
        h_sh[p][j] = hn; c_sh[p][j] = cn;
        outs[(size_t)((q * 21 + p) * 32 + t) * 64 + dir * 32 + j] = hn;
        __syncthreads();
    }
}

// ---------------- attention + CE + acc ----------------
__global__ void __launch_bounds__(256) final_kernel(
    const float* __restrict__ outs,
    const int* __restrict__ ysup, const int* __restrict__ yqry,
    float* __restrict__ out)
{
    __shared__ float ce_sh[160], eq_sh[160];
    int tid = threadIdx.x;
    if (tid < 160) {
        int q = tid / 32, b = tid % 32;
        const float* qry = outs + (size_t)((q * 21 + 20) * 32 + b) * 64;
        float logit[20];
        for (int s = 0; s < 20; s++) {
            const float* sp = outs + (size_t)((q * 21 + s) * 32 + b) * 64;
            float d = 0.f, n2 = 0.f;
            for (int k = 0; k < 64; k++) { d += qry[k] * sp[k]; n2 += sp[k] * sp[k]; }
            logit[s] = d * rsqrtf(fmaxf(n2, 1e-10f));
        }
        float mx = logit[0];
        for (int s = 1; s < 20; s++) mx = fmaxf(mx, logit[s]);
        float den = 0.f;
        for (int s = 0; s < 20; s++) { logit[s] = expf(logit[s] - mx); den += logit[s]; }
        float invden = 1.f / den;
        float preds[20];
        for (int wq = 0; wq < 20; wq++) preds[wq] = 0.f;
        for (int s = 0; s < 20; s++) preds[ysup[b * 20 + s]] += logit[s] * invden;
        int yq = yqry[b * 5 + q];
        float pv = fminf(fmaxf(preds[yq], 1e-7f), 1.f - 1e-7f);
        ce_sh[tid] = -logf(pv);
        int best = 0;
        for (int wq = 1; wq < 20; wq++) if (preds[wq] > preds[best]) best = wq;
        eq_sh[tid] = (best == yq) ? 1.f : 0.f;
    }
    __syncthreads();
    if (tid < 32) {
        float s = 0.f;
        for (int q = 0; q < 5; q++) s += ce_sh[q * 32 + tid];
        out[tid] = s * 0.2f;
    }
    if (tid == 0) {
        float s = 0.f;
        for (int i = 0; i < 160; i++) s += eq_sh[i];
        out[32] = s / 160.f;
    }
}

// ---------------- launch ----------------
extern "C" void kernel_launch(void* const* d_in, const int* in_sizes, int n_in,
                              void* d_out, int out_size)
{
    (void)in_sizes; (void)n_in; (void)out_size;
    const float* xs = (const float*)d_in[0];
    const int* ysup = (const int*)d_in[1];
    const float* xq = (const float*)d_in[2];
    const int* yqry = (const int*)d_in[3];
    const float *k1=(const float*)d_in[4],  *b1=(const float*)d_in[5],  *g1=(const float*)d_in[6],  *be1=(const float*)d_in[7];
    const float *k2=(const float*)d_in[8],  *b2=(const float*)d_in[9],  *g2=(const float*)d_in[10], *be2=(const float*)d_in[11];
    const float *k3=(const float*)d_in[12], *b3=(const float*)d_in[13], *g3=(const float*)d_in[14], *be3=(const float*)d_in[15];
    const float *k4=(const float*)d_in[16], *b4=(const float*)d_in[17], *g4=(const float*)d_in[18], *be4=(const float*)d_in[19];
    const float *fk=(const float*)d_in[20], *fr=(const float*)d_in[21], *fb=(const float*)d_in[22];
    const float *bk=(const float*)d_in[23], *br=(const float*)d_in[24], *bb=(const float*)d_in[25];

    float *pool1, *raw, *pool2, *pool3, *pool4, *part, *Z, *outs, *ab;
    cudaGetSymbolAddress((void**)&pool1, g_pool1);
    cudaGetSymbolAddress((void**)&raw, g_raw);
    cudaGetSymbolAddress((void**)&pool2, g_pool2);
    cudaGetSymbolAddress((void**)&pool3, g_pool3);
    cudaGetSymbolAddress((void**)&pool4, g_pool4);
    cudaGetSymbolAddress((void**)&part, g_part);
    cudaGetSymbolAddress((void**)&Z, g_Z);
    cudaGetSymbolAddress((void**)&outs, g_outs);
    cudaGetSymbolAddress((void**)&ab, g_ab);

    const int SM42 = 1024 + 2 * 9 * 64 * 144 + 2 * (2 * 44 + 132) * 144;  // 230272
    const int SM21 = 1024 + 2 * 9 * 64 * 144 + 2 * (2 * 23 + 132) * 144;  // 218176
    const int SM10 = 1024 + 2 * 9 * 64 * 144 + 2 * (2 * 12 + 132) * 144;  // 211840
    cudaFuncSetAttribute(mmaconv_kernel<42,16>, cudaFuncAttributeMaxDynamicSharedMemorySize, SM42);
    cudaFuncSetAttribute(mmaconv_kernel<21,5>,  cudaFuncAttributeMaxDynamicSharedMemorySize, SM21);
    cudaFuncSetAttribute(mmaconv_kernel<10,2>,  cudaFuncAttributeMaxDynamicSharedMemorySize, SM10);

    // L1: SIMT conv 84 -> pooled CL 42 + stats partials
    convpool1_kernel<<<dim3(6, 11, NIMG), 128>>>(xs, xq, k1, b1, pool1, part);
    abreduce_kernel<<<25 * 64, 256>>>(part, g1, be1, ab, 66, 1.f / (32.f * 84.f * 84.f));
    // L2: mma conv on 42 (stats fused)
    mmaconv_kernel<42,16><<<NIMG, 256, SM42>>>(pool1, ab, k2, b2, raw, part);
    poolCL_kernel<42><<<(NIMG*441*64 + 255)/256, 256>>>(raw, pool2);
    abfin2_kernel<<<25, 64>>>(part, g2, be2, ab, 1.f / (32.f * 1764.f));
    // L3: mma conv on 21
    mmaconv_kernel<21,5><<<NIMG, 256, SM21>>>(pool2, ab, k3, b3, raw, part);
    poolCL_kernel<21><<<(NIMG*100*64 + 255)/256, 256>>>(raw, pool3);
    abfin2_kernel<<<25, 64>>>(part, g3, be3, ab, 1.f / (32.f * 441.f));
    // L4: mma conv on 10
    mmaconv_kernel<10,2><<<NIMG, 256, SM10>>>(pool3, ab, k4, b4, raw, part);
    poolCL_kernel<10><<<(NIMG*25*64 + 255)/256, 256>>>(raw, pool4);
    abfin2_kernel<<<25, 64>>>(part, g4, be4, ab, 1.f / (32.f * 100.f));

    gemmz_kernel<<<dim3(25, 2), 256>>>(pool4, ab, fk, fb, bk, bb, Z);
    lstm_kernel<<<dim3(5, 2), 672>>>(Z, fr, br, outs);
    final_kernel<<<1, 256>>>(outs, ysup, yqry, (float*)d_out);
}

// round 9
// speedup vs baseline: 2.1795x; 1.4997x over previous
#include <cuda_runtime.h>
#include <cuda_fp16.h>
#include <math.h>
#include <stdint.h>

#define NIMG 800
typedef unsigned long long u64;

// ---------------- scratch ----------------
__device__ float g_pool1[(size_t)NIMG * 1764 * 64];
__device__ float g_raw  [(size_t)NIMG * 1764 * 64];
__device__ float g_pool2[(size_t)NIMG * 441 * 64];
__device__ float g_pool3[(size_t)NIMG * 100 * 64];
__device__ float g_pool4[(size_t)NIMG * 25 * 64];
__device__ float g_part [(size_t)NIMG * 66 * 128];   // L1 tile partials; L2-4: [g][128]
__device__ float g_Z[2 * NIMG * 128];
__device__ float g_outs[5 * 21 * 32 * 64];
__device__ float g_ab[25 * 64 * 2];

// ---------------- f32x2 helpers (layer-1 SIMT) ----------------
__device__ __forceinline__ u64 pack_dup(float v) {
    u64 r; asm("mov.b64 %0, {%1, %1};" : "=l"(r) : "f"(v)); return r;
}
__device__ __forceinline__ void ffma2(u64& acc, u64 a, u64 b) {
    asm("fma.rn.f32x2 %0, %1, %2, %0;" : "+l"(acc) : "l"(a), "l"(b));
}
__device__ __forceinline__ void unpack2(u64 v, float& lo, float& hi) {
    asm("mov.b64 {%0, %1}, %2;" : "=f"(lo), "=f"(hi) : "l"(v));
}

// ---------------- warp mma (fp16 in, f32 acc) ----------------
__device__ __forceinline__ void mma16816(float* d, uint32_t a0, uint32_t a1,
                                         uint32_t a2, uint32_t a3,
                                         uint32_t b0, uint32_t b1) {
    asm volatile(
        "mma.sync.aligned.m16n8k16.row.col.f32.f16.f16.f32 "
        "{%0,%1,%2,%3}, {%4,%5,%6,%7}, {%8,%9}, {%0,%1,%2,%3};"
        : "+f"(d[0]), "+f"(d[1]), "+f"(d[2]), "+f"(d[3])
        : "r"(a0), "r"(a1), "r"(a2), "r"(a3), "r"(b0), "r"(b1));
}

// ================= mmaconv: layers 2-4, one block per image, 256 thr =================
// fp16 path: A = act split hi/lo (2 passes), B = weights single fp16.
// 256-row output tiles; 8 warps x (2 mtiles x 8 ntiles).
template <int NX, int NT>
__global__ void __launch_bounds__(256) mmaconv_kernel(
    const float* __restrict__ in, const float* __restrict__ abp,
    const float* __restrict__ w, const float* __restrict__ bias,
    float* __restrict__ raw, float* __restrict__ part)
{
    constexpr int W = NX + 2, P = W * W, PIX = NX * NX;
    constexpr int ROWS = 2 * W + 260;         // >= 256 + 2W + 3
    constexpr int SROW = 144;
    constexpr int BTAP = 64 * SROW;
    constexpr int OFF_B  = 1024;
    constexpr int OFF_SH = OFF_B + 9 * BTAP;  // A hi staging
    constexpr int OFF_SL = OFF_SH + ROWS * SROW;

    extern __shared__ __align__(16) char smem[];
    int tid = threadIdx.x;
    int g = blockIdx.x, slot = g >> 5;
    float* bias_sh = (float*)(smem + 16);
    float* ab_sh   = (float*)(smem + 304);
    if (tid < 64) bias_sh[tid] = bias[tid];
    if (tid < 128) ab_sh[tid] = abp[slot * 128 + tid];

    // B fill: w[t][ci][oc] -> B[t][oc][ci] fp16
    for (int i = tid; i < 9 * 64 * 64; i += 256) {
        int t = i >> 12, r = i & 4095, ci = r >> 6, oc = r & 63;
        *(__half*)(smem + OFF_B + (t * 64 + oc) * SROW + ci * 2) = __float2half_rn(w[i]);
    }

    int warp = tid >> 5, lane = tid & 31;
    int g_row = lane >> 2, four = lane & 3;
    int mbase = warp * 32;                    // 8 warps x 32 rows = 256

    float ps[8][2], qs[8][2];
#pragma unroll
    for (int nt = 0; nt < 8; nt++) { ps[nt][0]=0.f; ps[nt][1]=0.f; qs[nt][0]=0.f; qs[nt][1]=0.f; }

    for (int tile = 0; tile < NT; tile++) {
        int s0 = tile * 256;
        __syncthreads();   // staging vs prev tile's compute
        // ---- stage strip: BN+relu prev, fp16 hi/lo split ----
        for (int i = tid; i < ROWS * 16; i += 256) {
            int r = i >> 4, c4 = (i & 15) * 4;
            int sp = s0 - W - 1 + r;
            float4 v = make_float4(0.f, 0.f, 0.f, 0.f);
            if (sp >= 0 && sp < P) {
                int py = sp / W, px = sp - py * W;
                if (px >= 1 && px <= NX && py >= 1 && py <= NX) {
                    float4 rv = *(const float4*)&in[((size_t)g * PIX + (py - 1) * NX + (px - 1)) * 64 + c4];
                    v.x = fmaxf(fmaf(ab_sh[(c4 + 0) * 2], rv.x, ab_sh[(c4 + 0) * 2 + 1]), 0.f);
                    v.y = fmaxf(fmaf(ab_sh[(c4 + 1) * 2], rv.y, ab_sh[(c4 + 1) * 2 + 1]), 0.f);
                    v.z = fmaxf(fmaf(ab_sh[(c4 + 2) * 2], rv.z, ab_sh[(c4 + 2) * 2 + 1]), 0.f);
                    v.w = fmaxf(fmaf(ab_sh[(c4 + 3) * 2], rv.w, ab_sh[(c4 + 3) * 2 + 1]), 0.f);
                }
            }
            __half hx = __float2half_rn(v.x), hy = __float2half_rn(v.y);
            __half hz = __float2half_rn(v.z), hw = __float2half_rn(v.w);
            __half lx = __float2half_rn(v.x - __half2float(hx));
            __half ly = __float2half_rn(v.y - __half2float(hy));
            __half lz = __float2half_rn(v.z - __half2float(hz));
            __half lw = __float2half_rn(v.w - __half2float(hw));
            __half2 h01 = __halves2half2(hx, hy), h23 = __halves2half2(hz, hw);
            __half2 l01 = __halves2half2(lx, ly), l23 = __halves2half2(lz, lw);
            *(uint2*)(smem + OFF_SH + r * SROW + c4 * 2) =
                make_uint2(*(uint32_t*)&h01, *(uint32_t*)&h23);
            *(uint2*)(smem + OFF_SL + r * SROW + c4 * 2) =
                make_uint2(*(uint32_t*)&l01, *(uint32_t*)&l23);
        }
        __syncthreads();

        // ---- compute: warp covers rows [mbase, mbase+32) x 64 oc ----
        float d[2][8][4];
#pragma unroll
        for (int mt = 0; mt < 2; mt++)
#pragma unroll
            for (int nt = 0; nt < 8; nt++)
#pragma unroll
                for (int i = 0; i < 4; i++) d[mt][nt][i] = 0.f;

#pragma unroll 1
        for (int pass = 0; pass < 2; pass++) {
            const char* abase = smem + (pass ? OFF_SL : OFF_SH);
#pragma unroll 1
            for (int t = 0; t < 9; t++) {
                int rshift = (t / 3) * W + (t % 3);
                const char* bt = smem + OFF_B + t * BTAP;
#pragma unroll
                for (int kc = 0; kc < 4; kc++) {
                    int cb = kc * 32 + four * 4;
                    uint32_t a[2][4];
#pragma unroll
                    for (int mt = 0; mt < 2; mt++) {
                        const char* ap = abase + (mbase + mt * 16 + rshift + g_row) * SROW + cb;
                        a[mt][0] = *(const uint32_t*)ap;
                        a[mt][1] = *(const uint32_t*)(ap + 8 * SROW);
                        a[mt][2] = *(const uint32_t*)(ap + 16);
                        a[mt][3] = *(const uint32_t*)(ap + 8 * SROW + 16);
                    }
#pragma unroll
                    for (int nt = 0; nt < 8; nt++) {
                        const char* bp = bt + (nt * 8 + g_row) * SROW + cb;
                        uint32_t b0 = *(const uint32_t*)bp;
                        uint32_t b1 = *(const uint32_t*)(bp + 16);
                        mma16816(d[0][nt], a[0][0], a[0][1], a[0][2], a[0][3], b0, b1);
                        mma16816(d[1][nt], a[1][0], a[1][1], a[1][2], a[1][3], b0, b1);
                    }
                }
            }
        }

        // ---- epilogue: bias, write valid rows channels-last, fused stats ----
#pragma unroll
        for (int mt = 0; mt < 2; mt++)
#pragma unroll
            for (int rr = 0; rr < 2; rr++) {
                int m = mbase + mt * 16 + g_row + rr * 8;
                int sp = s0 + m;
                bool ok = false;
                float* o = 0;
                if (sp < P) {
                    int py = sp / W, px = sp - py * W;
                    if (px >= 1 && px <= NX && py >= 1 && py <= NX) {
                        ok = true;
                        o = raw + ((size_t)g * PIX + (py - 1) * NX + (px - 1)) * 64;
                    }
                }
#pragma unroll
                for (int nt = 0; nt < 8; nt++) {
                    int oc = nt * 8 + four * 2;
                    float vx = d[mt][nt][rr * 2]     + bias_sh[oc];
                    float vy = d[mt][nt][rr * 2 + 1] + bias_sh[oc + 1];
                    if (ok) {
                        *(float2*)(o + oc) = make_float2(vx, vy);
                        ps[nt][0] += vx; qs[nt][0] += vx * vx;
                        ps[nt][1] += vy; qs[nt][1] += vy * vy;
                    }
                }
            }
    }

    // ---- stats reduction: lanes (over g_row), then warps, -> part[g][128] ----
#pragma unroll
    for (int nt = 0; nt < 8; nt++)
#pragma unroll
        for (int j = 0; j < 2; j++) {
#pragma unroll
            for (int off = 16; off >= 4; off >>= 1) {
                ps[nt][j] += __shfl_down_sync(~0u, ps[nt][j], off);
                qs[nt][j] += __shfl_down_sync(~0u, qs[nt][j], off);
            }
        }
    __syncthreads();
    float* wst = (float*)(smem + OFF_SH);
    if (lane < 4) {
#pragma unroll
        for (int nt = 0; nt < 8; nt++)
#pragma unroll
            for (int j = 0; j < 2; j++) {
                int oc = nt * 8 + lane * 2 + j;
                wst[warp * 128 + oc]      = ps[nt][j];
                wst[warp * 128 + 64 + oc] = qs[nt][j];
            }
    }
    __syncthreads();
    if (tid < 128) {
        float s = 0.f;
#pragma unroll
        for (int wi = 0; wi < 8; wi++) s += wst[wi * 128 + tid];
        part[(size_t)g * 128 + tid] = s;
    }
}

// ---------------- per-slot BN affine from per-image partials [g][128] ----------------
__global__ void __launch_bounds__(64) abfin2_kernel(const float* __restrict__ part,
    const float* __restrict__ gamma, const float* __restrict__ beta,
    float* __restrict__ ab, float invCnt)
{
    int slot = blockIdx.x, c = threadIdx.x;
    float s = 0.f, q = 0.f;
    for (int b = 0; b < 32; b++) {
        s += part[(size_t)(slot * 32 + b) * 128 + c];
        q += part[(size_t)(slot * 32 + b) * 128 + 64 + c];
    }
    float mn = s * invCnt;
    float var = q * invCnt - mn * mn;
    float sc = gamma[c] * rsqrtf(var + 1e-3f);
    ab[(slot * 64 + c) * 2] = sc;
    ab[(slot * 64 + c) * 2 + 1] = beta[c] - mn * sc;
}

// ---------------- 2x2 maxpool on channels-last raw (pre-BN, exact) ----------------
template <int NX>
__global__ void __launch_bounds__(256) poolCL_kernel(const float* __restrict__ raw,
                                                    float* __restrict__ out)
{
    constexpr int Np = NX / 2;
    long idx = (long)blockIdx.x * 256 + threadIdx.x;
    if (idx >= (long)NIMG * Np * Np * 64) return;
    int c = (int)(idx & 63); long t = idx >> 6;
    int ox = (int)(t % Np); t /= Np;
    int oy = (int)(t % Np); int g = (int)(t / Np);
    const float* p = raw + ((size_t)g * NX * NX + (2 * oy) * NX + 2 * ox) * 64 + c;
    float v = fmaxf(fmaxf(p[0], p[64]), fmaxf(p[(size_t)NX * 64], p[(size_t)NX * 64 + 64]));
    out[idx] = v;
}

// ---------------- layer 1 SIMT conv + partials + pre-BN pool (channels-last out) ----------------
__device__ __forceinline__ void epi1(
    u64 (&acc)[8][4], int g, int x0, int y0, int px, int oc0,
    float* __restrict__ pooled, float* __restrict__ part)
{
    const int N = 84, Np = 42;
    int T = gridDim.x * gridDim.y;
    int tile = blockIdx.y * gridDim.x + blockIdx.x;
    bool xv = (x0 + px) < N;
    float* partp = part + ((size_t)(g * T + tile) * 64 + oc0) * 2;
    int pooly0 = y0 >> 1, poolx = (x0 + px) >> 1;
#pragma unroll
    for (int j = 0; j < 4; j++) {
        float s0 = 0.f, s1 = 0.f, q0 = 0.f, q1 = 0.f;
        float m0[4], m1[4];
#pragma unroll
        for (int jj = 0; jj < 4; jj++) { m0[jj] = -1e30f; m1[jj] = -1e30f; }
#pragma unroll
        for (int p = 0; p < 8; p++) {
            float v0, v1; unpack2(acc[p][j], v0, v1);
            if (xv && (y0 + p) < N) { s0 += v0; q0 += v0 * v0; s1 += v1; q1 += v1 * v1; }
            m0[p >> 1] = fmaxf(m0[p >> 1], v0);
            m1[p >> 1] = fmaxf(m1[p >> 1], v1);
        }
#pragma unroll
        for (int off = 8; off; off >>= 1) {
            s0 += __shfl_down_sync(~0u, s0, off, 16); s1 += __shfl_down_sync(~0u, s1, off, 16);
            q0 += __shfl_down_sync(~0u, q0, off, 16); q1 += __shfl_down_sync(~0u, q1, off, 16);
        }
        if (px == 0) {
            partp[(2*j)*2] = s0; partp[(2*j)*2+1] = q0;
            partp[(2*j+1)*2] = s1; partp[(2*j+1)*2+1] = q1;
        }
#pragma unroll
        for (int jj = 0; jj < 4; jj++) {
            float o0 = __shfl_xor_sync(~0u, m0[jj], 1);
            float o1 = __shfl_xor_sync(~0u, m1[jj], 1);
            if (!(px & 1)) {
                int py = pooly0 + jj;
                if (py < Np && poolx < Np) {
                    float* o = pooled + ((size_t)g * Np * Np + py * Np + poolx) * 64;
                    o[oc0 + 2*j] = fmaxf(m0[jj], o0);
                    o[oc0 + 2*j + 1] = fmaxf(m1[jj], o1);
                }
            }
        }
    }
}

__global__ void __launch_bounds__(128, 4) convpool1_kernel(
    const float* __restrict__ xs, const float* __restrict__ xq,
    const float* __restrict__ w, const float* __restrict__ bias,
    float* __restrict__ pooled, float* __restrict__ part)
{
    const int N = 84;
    __shared__ __align__(16) float w_sh[9][3][64];
    __shared__ float in_sh[3][10][20];
    int g = blockIdx.z;
    int x0 = blockIdx.x * 16, y0 = blockIdx.y * 8;
    int tid = threadIdx.x;
    int px = tid & 15, oc0 = (tid >> 4) * 8;
    u64 acc[8][4];
    {
        ulonglong2 b0 = *(const ulonglong2*)&bias[oc0];
        ulonglong2 b1 = *(const ulonglong2*)&bias[oc0 + 4];
#pragma unroll
        for (int p = 0; p < 8; p++) { acc[p][0]=b0.x; acc[p][1]=b0.y; acc[p][2]=b1.x; acc[p][3]=b1.y; }
    }
    for (int i = tid; i < 9 * 3 * 64; i += 128) {
        int kk = i / 192, r = i % 192;
        w_sh[kk][r / 64][r % 64] = w[i];
    }
    int b = g & 31, slot = g >> 5;
    const float* src = (slot < 20)
        ? (xs + (size_t)(b * 20 + slot) * 84 * 84 * 3)
        : (xq + (size_t)(b * 5 + (slot - 20)) * 84 * 84 * 3);
    for (int i = tid; i < 3 * 10 * 18; i += 128) {
        int cc = i / 180, r = i % 180, yy = r / 18, xx = r % 18;
        int gy = y0 + yy - 1, gx = x0 + xx - 1;
        float v = 0.f;
        if (gy >= 0 && gy < N && gx >= 0 && gx < N) v = src[(size_t)(gy * 84 + gx) * 3 + cc];
        in_sh[cc][yy][xx] = v;
    }
    __syncthreads();
#pragma unroll
    for (int cc = 0; cc < 3; cc++)
#pragma unroll
        for (int kx = 0; kx < 3; kx++) {
            u64 a[10];
#pragma unroll
            for (int r = 0; r < 10; r++) a[r] = pack_dup(in_sh[cc][r][px + kx]);
#pragma unroll
            for (int ky = 0; ky < 3; ky++) {
                int kk = ky * 3 + kx;
                ulonglong2 w01 = *(const ulonglong2*)&w_sh[kk][cc][oc0];
                ulonglong2 w23 = *(const ulonglong2*)&w_sh[kk][cc][oc0 + 4];
#pragma unroll
                for (int p = 0; p < 8; p++) {
                    ffma2(acc[p][0], a[p + ky], w01.x); ffma2(acc[p][1], a[p + ky], w01.y);
                    ffma2(acc[p][2], a[p + ky], w23.x); ffma2(acc[p][3], a[p + ky], w23.y);
                }
            }
        }
    epi1(acc, g, x0, y0, px, oc0, pooled, part);
}

// L1 partial reduce (tile-indexed layout)
__global__ void __launch_bounds__(256) abreduce_kernel(
    const float* __restrict__ part,
    const float* __restrict__ gamma, const float* __restrict__ beta,
    float* __restrict__ ab, int T, float invCnt)
{
    int slot = blockIdx.x >> 6, c = blockIdx.x & 63;
    int tid = threadIdx.x;
    float s = 0.f, q = 0.f;
    int total = 32 * T;
    for (int i = tid; i < total; i += 256) {
        const float* p = part + ((size_t)(slot * 32 + i / T) * T + i % T) * 128 + c * 2;
        s += p[0]; q += p[1];
    }
    __shared__ float sh1[256], sh2[256];
    sh1[tid] = s; sh2[tid] = q;
    __syncthreads();
    for (int st = 128; st > 0; st >>= 1) {
        if (tid < st) { sh1[tid] += sh1[tid + st]; sh2[tid] += sh2[tid + st]; }
        __syncthreads();
    }
    if (tid == 0) {
        float m = sh1[0] * invCnt;
        float var = sh2[0] * invCnt - m * m;
        float sc = gamma[c] * rsqrtf(var + 1e-3f);
        ab[blockIdx.x * 2] = sc;
        ab[blockIdx.x * 2 + 1] = beta[c] - m * sc;
    }
}

// ---------------- gemmz (pool4 channels-last: d = pix*64 + c directly) ----------------
__global__ void __launch_bounds__(256) gemmz_kernel(
    const float* __restrict__ emb, const float* __restrict__ abp,
    const float* __restrict__ fk, const float* __restrict__ fb,
    const float* __restrict__ bk, const float* __restrict__ bb,
    float* __restrict__ Z)
{
    int gb = blockIdx.x, dir = blockIdx.y;
    const float* W = dir ? bk : fk;
    const float* bias = dir ? bb : fb;
    float* Zo = Z + (size_t)dir * NIMG * 128;
    __shared__ float A_sh[32][33];
    __shared__ __align__(16) float B_sh[32][128];
    int tid = threadIdx.x, jj = tid & 31, gg = tid >> 5;
    float acc[4][4] = {};
    for (int d0 = 0; d0 < 1600; d0 += 32) {
        for (int i = tid; i < 1024; i += 256) {
            int r = i >> 5, dd = i & 31, d = d0 + dd, c = d & 63;
            float raw = emb[(size_t)(gb * 32 + r) * 1600 + d];
            A_sh[r][dd] = fmaxf(fmaf(abp[(gb * 64 + c) * 2], raw, abp[(gb * 64 + c) * 2 + 1]), 0.f);
        }
        for (int i = tid; i < 4096; i += 256)
            B_sh[i >> 7][i & 127] = W[(size_t)(d0 + (i >> 7)) * 128 + (i & 127)];
        __syncthreads();
#pragma unroll
        for (int dd = 0; dd < 32; dd++) {
            float4 bv = *(const float4*)&B_sh[dd][jj * 4];
#pragma unroll
            for (int r = 0; r < 4; r++) {
                float a = A_sh[gg * 4 + r][dd];
                acc[r][0] += a * bv.x; acc[r][1] += a * bv.y;
                acc[r][2] += a * bv.z; acc[r][3] += a * bv.w;
            }
        }
        __syncthreads();
    }
#pragma unroll
    for (int r = 0; r < 4; r++)
#pragma unroll
        for (int c = 0; c < 4; c++)
            Zo[(size_t)(gb * 32 + gg * 4 + r) * 128 + jj * 4 + c] = acc[r][c] + bias[jj * 4 + c];
}

// ---------------- LSTM ----------------
__global__ void __launch_bounds__(672) lstm_kernel(
    const float* __restrict__ Z,
    const float* __restrict__ fr, const float* __restrict__ br,
    float* __restrict__ outs)
{
    int q = blockIdx.x, dir = blockIdx.y;
    const float* R = dir ? br : fr;
    const float* Zp = Z + (size_t)dir * NIMG * 128;
    __shared__ float Wh[32][128];
    __shared__ float h_sh[21][32], c_sh[21][32];
    int tid = threadIdx.x;
    for (int i = tid; i < 4096; i += 672) Wh[i >> 7][i & 127] = R[i];
    int p = tid >> 5, j = tid & 31;
    h_sh[p][j] = 0.f; c_sh[p][j] = 0.f;
    __syncthreads();
    int slot = (p < 20) ? p : (20 + q);
    for (int step = 0; step < 32; step++) {
        int t = dir ? (31 - step) : step;
        const float* zr = Zp + (size_t)(slot * 32 + t) * 128;
        float z0 = zr[j], z1 = zr[32 + j], z2 = zr[64 + j], z3 = zr[96 + j];
#pragma unroll
        for (int k = 0; k < 32; k++) {
            float hk = h_sh[p][k];
            z0 += hk * Wh[k][j]; z1 += hk * Wh[k][32 + j];
            z2 += hk * Wh[k][64 + j]; z3 += hk * Wh[k][96 + j];
        }
        float ig = 1.f / (1.f + expf(-z0)), fg = 1.f / (1.f + expf(-z1));
        float gg = tanhf(z2), og = 1.f / (1.f + expf(-z3));
        float cn = fg * c_sh[p][j] + ig * gg;
        float hn = og * tanhf(cn);
        __syncthreads();
        h_sh[p][j] = hn; c_sh[p][j] = cn;
        outs[(size_t)((q * 21 + p) * 32 + t) * 64 + dir * 32 + j] = hn;
        __syncthreads();
    }
}

// ---------------- attention + CE + acc ----------------
__global__ void __launch_bounds__(256) final_kernel(
    const float* __restrict__ outs,
    const int* __restrict__ ysup, const int* __restrict__ yqry,
    float* __restrict__ out)
{
    __shared__ float ce_sh[160], eq_sh[160];
    int tid = threadIdx.x;
    if (tid < 160) {
        int q = tid / 32, b = tid % 32;
        const float* qry = outs + (size_t)((q * 21 + 20) * 32 + b) * 64;
        float logit[20];
        for (int s = 0; s < 20; s++) {
            const float* sp = outs + (size_t)((q * 21 + s) * 32 + b) * 64;
            float d = 0.f, n2 = 0.f;
            for (int k = 0; k < 64; k++) { d += qry[k] * sp[k]; n2 += sp[k] * sp[k]; }
            logit[s] = d * rsqrtf(fmaxf(n2, 1e-10f));
        }
        float mx = logit[0];
        for (int s = 1; s < 20; s++) mx = fmaxf(mx, logit[s]);
        float den = 0.f;
        for (int s = 0; s < 20; s++) { logit[s] = expf(logit[s] - mx); den += logit[s]; }
        float invden = 1.f / den;
        float preds[20];
        for (int wq = 0; wq < 20; wq++) preds[wq] = 0.f;
        for (int s = 0; s < 20; s++) preds[ysup[b * 20 + s]] += logit[s] * invden;
        int yq = yqry[b * 5 + q];
        float pv = fminf(fmaxf(preds[yq], 1e-7f), 1.f - 1e-7f);
        ce_sh[tid] = -logf(pv);
        int best = 0;
        for (int wq = 1; wq < 20; wq++) if (preds[wq] > preds[best]) best = wq;
        eq_sh[tid] = (best == yq) ? 1.f : 0.f;
    }
    __syncthreads();
    if (tid < 32) {
        float s = 0.f;
        for (int q = 0; q < 5; q++) s += ce_sh[q * 32 + tid];
        out[tid] = s * 0.2f;
    }
    if (tid == 0) {
        float s = 0.f;
        for (int i = 0; i < 160; i++) s += eq_sh[i];
        out[32] = s / 160.f;
    }
}

// ---------------- launch ----------------
extern "C" void kernel_launch(void* const* d_in, const int* in_sizes, int n_in,
                              void* d_out, int out_size)
{
    (void)in_sizes; (void)n_in; (void)out_size;
    const float* xs = (const float*)d_in[0];
    const int* ysup = (const int*)d_in[1];
    const float* xq = (const float*)d_in[2];
    const int* yqry = (const int*)d_in[3];
    const float *k1=(const float*)d_in[4],  *b1=(const float*)d_in[5],  *g1=(const float*)d_in[6],  *be1=(const float*)d_in[7];
    const float *k2=(const float*)d_in[8],  *b2=(const float*)d_in[9],  *g2=(const float*)d_in[10], *be2=(const float*)d_in[11];
    const float *k3=(const float*)d_in[12], *b3=(const float*)d_in[13], *g3=(const float*)d_in[14], *be3=(const float*)d_in[15];
    const float *k4=(const float*)d_in[16], *b4=(const float*)d_in[17], *g4=(const float*)d_in[18], *be4=(const float*)d_in[19];
    const float *fk=(const float*)d_in[20], *fr=(const float*)d_in[21], *fb=(const float*)d_in[22];
    const float *bk=(const float*)d_in[23], *br=(const float*)d_in[24], *bb=(const float*)d_in[25];

    float *pool1, *raw, *pool2, *pool3, *pool4, *part, *Z, *outs, *ab;
    cudaGetSymbolAddress((void**)&pool1, g_pool1);
    cudaGetSymbolAddress((void**)&raw, g_raw);
    cudaGetSymbolAddress((void**)&pool2, g_pool2);
    cudaGetSymbolAddress((void**)&pool3, g_pool3);
    cudaGetSymbolAddress((void**)&pool4, g_pool4);
    cudaGetSymbolAddress((void**)&part, g_part);
    cudaGetSymbolAddress((void**)&Z, g_Z);
    cudaGetSymbolAddress((void**)&outs, g_outs);
    cudaGetSymbolAddress((void**)&ab, g_ab);

    // smem: 1024 hdr + 9*64*144 (B fp16) + 2 * (2W+260)*144 (staging hi/lo fp16)
    const int SM42 = 1024 + 9 * 64 * 144 + 2 * (2 * 44 + 260) * 144;  // 184192
    const int SM21 = 1024 + 9 * 64 * 144 + 2 * (2 * 23 + 260) * 144;  // 172096
    const int SM10 = 1024 + 9 * 64 * 144 + 2 * (2 * 12 + 260) * 144;  // 165760
    cudaFuncSetAttribute(mmaconv_kernel<42,8>, cudaFuncAttributeMaxDynamicSharedMemorySize, SM42);
    cudaFuncSetAttribute(mmaconv_kernel<21,3>, cudaFuncAttributeMaxDynamicSharedMemorySize, SM21);
    cudaFuncSetAttribute(mmaconv_kernel<10,1>, cudaFuncAttributeMaxDynamicSharedMemorySize, SM10);

    // L1: SIMT conv 84 -> pooled CL 42 + stats partials
    convpool1_kernel<<<dim3(6, 11, NIMG), 128>>>(xs, xq, k1, b1, pool1, part);
    abreduce_kernel<<<25 * 64, 256>>>(part, g1, be1, ab, 66, 1.f / (32.f * 84.f * 84.f));
    // L2: mma conv on 42 (stats fused)
    mmaconv_kernel<42,8><<<NIMG, 256, SM42>>>(pool1, ab, k2, b2, raw, part);
    poolCL_kernel<42><<<(NIMG*441*64 + 255)/256, 256>>>(raw, pool2);
    abfin2_kernel<<<25, 64>>>(part, g2, be2, ab, 1.f / (32.f * 1764.f));
    // L3: mma conv on 21
    mmaconv_kernel<21,3><<<NIMG, 256, SM21>>>(pool2, ab, k3, b3, raw, part);
    poolCL_kernel<21><<<(NIMG*100*64 + 255)/256, 256>>>(raw, pool3);
    abfin2_kernel<<<25, 64>>>(part, g3, be3, ab, 1.f / (32.f * 441.f));
    // L4: mma conv on 10
    mmaconv_kernel<10,1><<<NIMG, 256, SM10>>>(pool3, ab, k4, b4, raw, part);
    poolCL_kernel<10><<<(NIMG*25*64 + 255)/256, 256>>>(raw, pool4);
    abfin2_kernel<<<25, 64>>>(part, g4, be4, ab, 1.f / (32.f * 100.f));

    gemmz_kernel<<<dim3(25, 2), 256>>>(pool4, ab, fk, fb, bk, bb, Z);
    lstm_kernel<<<dim3(5, 2), 672>>>(Z, fr, br, outs);
    final_kernel<<<1, 256>>>(outs, ysup, yqry, (float*)d_out);
}